// round 10
// baseline (speedup 1.0000x reference)
#include <cuda_runtime.h>
#include <cuda_bf16.h>
#include <cstdint>

#define NN   100000
#define D    128
#define EH   600000
#define RRG  8
#define RHET 4
#define EREL 150000

// ---- scratch (device globals: no cudaMalloc allowed) ----
__device__ float g_h  [NN * D];                     // 51.2 MB
__device__ float g_agg[NN * D];                     // 51.2 MB
__device__ float g_rb [(size_t)NN * RRG * D];       // 409.6 MB relation-major [r][n][128]
__device__ float g_hb [(size_t)NN * RHET * D];      // 204.8 MB relation-major
// 28 weight matrices, each: bf16 hi block [128k][136] then lo block (272B rows)
#define WROW    272
#define WHALF   34816               // 128 * 272
#define WSTRIDE 69632               // hi + lo
__device__ unsigned char g_wprep[28 * WSTRIDE];

__device__ __forceinline__ float* selbuf(int w, float* dflt) {
    switch (w) {
        case 1: return g_h;
        case 2: return g_agg;
        case 3: return g_rb;
        case 4: return g_hb;
        default: return dflt;
    }
}

// ============================ PTX helpers ==================================
__device__ __forceinline__ uint32_t smem_u32(const void* p) {
    uint32_t a;
    asm("{ .reg .u64 t; cvta.to.shared.u64 t, %1; cvt.u32.u64 %0, t; }" : "=r"(a) : "l"(p));
    return a;
}
__device__ __forceinline__ void ldsm4(uint32_t a, uint32_t* r) {
    asm volatile("ldmatrix.sync.aligned.m8n8.x4.shared.b16 {%0,%1,%2,%3}, [%4];"
                 : "=r"(r[0]), "=r"(r[1]), "=r"(r[2]), "=r"(r[3]) : "r"(a));
}
__device__ __forceinline__ void ldsm4t(uint32_t a, uint32_t* r) {
    asm volatile("ldmatrix.sync.aligned.m8n8.x4.trans.shared.b16 {%0,%1,%2,%3}, [%4];"
                 : "=r"(r[0]), "=r"(r[1]), "=r"(r[2]), "=r"(r[3]) : "r"(a));
}
__device__ __forceinline__ void mma_bf16(float* d, const uint32_t* a, const uint32_t* b) {
    asm volatile(
        "mma.sync.aligned.m16n8k16.row.col.f32.bf16.bf16.f32 "
        "{%0,%1,%2,%3}, {%4,%5,%6,%7}, {%8,%9}, {%0,%1,%2,%3};"
        : "+f"(d[0]), "+f"(d[1]), "+f"(d[2]), "+f"(d[3])
        : "r"(a[0]), "r"(a[1]), "r"(a[2]), "r"(a[3]), "r"(b[0]), "r"(b[1]));
}
__device__ __forceinline__ uint32_t pk_bf16x2(float lo, float hi) {
    uint32_t r;
    asm("cvt.rn.bf16x2.f32 %0, %1, %2;" : "=r"(r) : "f"(hi), "f"(lo));
    return r;
}
__device__ __forceinline__ float bfbits2f(uint32_t b16) { return __uint_as_float(b16 << 16); }
__device__ __forceinline__ void cp_async16(uint32_t saddr, const void* gaddr) {
    asm volatile("cp.async.ca.shared.global [%0], [%1], 16;"
                 :: "r"(saddr), "l"(gaddr) : "memory");
}
__device__ __forceinline__ void cp_commit() {
    asm volatile("cp.async.commit_group;" ::: "memory");
}
__device__ __forceinline__ void cp_wait0() {
    asm volatile("cp.async.wait_group 0;" ::: "memory");
}

// ============================ simple kernels ===============================
__global__ void __launch_bounds__(256) zero_kernel(int which, int start4, int n4) {
    float4* p = (float4*)selbuf(which, nullptr) + start4;
    int i = blockIdx.x * blockDim.x + threadIdx.x;
    int stride = gridDim.x * blockDim.x;
    float4 z = make_float4(0.f, 0.f, 0.f, 0.f);
    for (; i < n4; i += stride) p[i] = z;
}

// Grid-stride warp-per-edge scatter. If et != null, only edges with
// et[e] == relSel are processed. Dest row = dstBase + dst[e].
__global__ void __launch_bounds__(256) scatter_kernel(
        int xWhich, const float* xExt,
        const int* __restrict__ src, const int* __restrict__ dst,
        const int* __restrict__ et, int relSel,
        int outWhich, int E, int dstBase) {
    int nw = (gridDim.x * blockDim.x) >> 5;
    int gw = (blockIdx.x * blockDim.x + threadIdx.x) >> 5;
    int lane = threadIdx.x & 31;
    const float4* x = (const float4*)selbuf(xWhich, (float*)xExt);
    float4* out = (float4*)selbuf(outWhich, nullptr);
    for (int e = gw; e < E; e += nw) {
        if (et && et[e] != relSel) continue;
        int s = src[e];
        int d = dst[e];
        float4 v = x[(size_t)s * 32 + lane];
        float4* o = out + ((size_t)(dstBase + d)) * 32 + lane;
        asm volatile("red.global.add.v4.f32 [%0], {%1,%2,%3,%4};"
                     :: "l"(o), "f"(v.x), "f"(v.y), "f"(v.z), "f"(v.w)
                     : "memory");
    }
}

// ============================ weight prep ==================================
// Split each fp32 [128k x 128c] matrix into bf16 hi/lo with 272-byte rows
// (136 bf16 stride): 272 mod 128 = 16 -> conflict-free ldmatrix.
__global__ void __launch_bounds__(128) prep_weights(
        const float* gcn_W1, const float* gcn_W2,
        const float* rg_W1, const float* rg_loop1,
        const float* rg_W2, const float* rg_loop2,
        const float* het_W1, const float* het_W2) {
    int blk = blockIdx.x;
    const float* W;
    if      (blk == 0)  W = gcn_W1;
    else if (blk == 1)  W = gcn_W2;
    else if (blk < 10)  W = rg_W1 + (size_t)(blk - 2) * 16384;
    else if (blk == 10) W = rg_loop1;
    else if (blk < 19)  W = rg_W2 + (size_t)(blk - 11) * 16384;
    else if (blk == 19) W = rg_loop2;
    else if (blk < 24)  W = het_W1 + (size_t)(blk - 20) * 16384;
    else                W = het_W2 + (size_t)(blk - 24) * 16384;

    __nv_bfloat16* dh = (__nv_bfloat16*)(g_wprep + (size_t)blk * WSTRIDE);
    __nv_bfloat16* dl = dh + WHALF / 2;
    int c = threadIdx.x;
    for (int k = 0; k < 128; k++) {
        float w = W[k * 128 + c];
        __nv_bfloat16 h = __float2bfloat16(w);
        __nv_bfloat16 l = __float2bfloat16(w - __bfloat162float(h));
        dh[k * 136 + c] = h;
        dl[k * 136 + c] = l;
    }
}

// ==================== HMMA GEMM, M32 warps (sum path) ======================
// 256 threads, 8 warps, CTA tile 128x128, warp tile 32x64.
// Two-phase W in one 34 KB buffer. smem = 2x34816 (A hi/lo) + 34816 (W).
// sliceA: A chunk ch at A + ch*NN*128 (relation-major) else interleaved.
#define M32_AH 0
#define M32_AL 34816
#define M32_W  69632
#define SMEM_M32 104448
#define KS 4352                     // 16 rows * 272

__global__ void __launch_bounds__(256, 2) tc_gemm32(
        int aWhich, const float* aExt, int nChunks, int wBase, int sliceA,
        int xWhich, const float* xExt, int xWIdx,
        const float* __restrict__ b,
        float* outExt, int outWhich) {
    extern __shared__ unsigned char smem[];
    uint32_t sb = smem_u32(smem);
    int t = threadIdx.x, wid = t >> 5, lane = t & 31;
    int wr = wid & 3, wc = wid >> 2;
    int n0 = blockIdx.x * 128;

    const float* A = selbuf(aWhich, (float*)aExt);
    const float* X = (xWIdx >= 0) ? selbuf(xWhich, (float*)xExt) : nullptr;
    float* out = selbuf(outWhich, outExt);

    float acc[2][8][4];
#pragma unroll
    for (int m = 0; m < 2; m++)
#pragma unroll
        for (int i = 0; i < 8; i++)
#pragma unroll
            for (int j = 0; j < 4; j++) acc[m][i][j] = 0.f;

    int tot = nChunks + (X ? 1 : 0);

    uint32_t lmrow = (uint32_t)(lane & 15) * 272 + (uint32_t)(lane >> 4) * 16;
    uint32_t aBase = sb + (uint32_t)wr * (2 * KS) + lmrow;  // + AH|AL + m*KS + ks*32
    uint32_t bBase = sb + M32_W + lmrow + (uint32_t)wc * 128; // + ks*KS + g*32

    for (int ch = 0; ch < tot; ch++) {
        const float* Asrc; int ld, kOff, wIdx;
        if (ch < nChunks) {
            if (sliceA) { Asrc = A + (size_t)ch * NN * 128; ld = 128; kOff = 0; }
            else        { Asrc = A; ld = nChunks * 128; kOff = ch * 128; }
            wIdx = wBase + ch;
        } else { Asrc = X; ld = 128; kOff = 0; wIdx = xWIdx; }

        const unsigned char* wimg = g_wprep + (size_t)wIdx * WSTRIDE;

        __syncthreads();
        // ---- async copy WH (34816 B = 2176 x 16B) ----
        for (int i = t; i < 2176; i += 256)
            cp_async16(sb + M32_W + (uint32_t)i * 16, wimg + (size_t)i * 16);
        cp_commit();
        // ---- stage A (128 rows): fp32 -> bf16 hi/lo (overlaps cp.async) ----
#pragma unroll
        for (int i = 0; i < 16; i++) {
            int f = t + i * 256;
            int row = f >> 5, c4 = f & 31;
            int rc = n0 + row; if (rc > NN - 1) rc = NN - 1;
            float4 v = *(const float4*)(Asrc + (size_t)rc * ld + kOff + c4 * 4);
            uint32_t h01 = pk_bf16x2(v.x, v.y);
            uint32_t h23 = pk_bf16x2(v.z, v.w);
            uint32_t l01 = pk_bf16x2(v.x - bfbits2f(h01 & 0xFFFFu),
                                     v.y - bfbits2f(h01 >> 16));
            uint32_t l23 = pk_bf16x2(v.z - bfbits2f(h23 & 0xFFFFu),
                                     v.w - bfbits2f(h23 >> 16));
            uint32_t off = (uint32_t)row * 272 + (uint32_t)c4 * 8;
            *(uint2*)(smem + M32_AH + off) = make_uint2(h01, h23);
            *(uint2*)(smem + M32_AL + off) = make_uint2(l01, l23);
        }
        cp_wait0();
        __syncthreads();

        // ---- phase 1: ah*bh + al*bh ----
#pragma unroll
        for (int ks = 0; ks < 8; ks++) {
            uint32_t ah0[4], ah1[4], al0[4], al1[4];
            ldsm4(aBase + M32_AH + ks * 32, ah0);
            ldsm4(aBase + M32_AH + KS + ks * 32, ah1);
            ldsm4(aBase + M32_AL + ks * 32, al0);
            ldsm4(aBase + M32_AL + KS + ks * 32, al1);
#pragma unroll
            for (int g = 0; g < 4; g++) {
                uint32_t bh[4];
                ldsm4t(bBase + (uint32_t)ks * KS + (uint32_t)g * 32, bh);
                mma_bf16(acc[0][g * 2],     ah0, bh);
                mma_bf16(acc[0][g * 2 + 1], ah0, bh + 2);
                mma_bf16(acc[1][g * 2],     ah1, bh);
                mma_bf16(acc[1][g * 2 + 1], ah1, bh + 2);
                mma_bf16(acc[0][g * 2],     al0, bh);
                mma_bf16(acc[0][g * 2 + 1], al0, bh + 2);
                mma_bf16(acc[1][g * 2],     al1, bh);
                mma_bf16(acc[1][g * 2 + 1], al1, bh + 2);
            }
        }
        __syncthreads();   // done reading WH
        for (int i = t; i < 2176; i += 256)
            cp_async16(sb + M32_W + (uint32_t)i * 16, wimg + WHALF + (size_t)i * 16);
        cp_commit();
        cp_wait0();
        __syncthreads();

        // ---- phase 2: ah*bl ----
#pragma unroll
        for (int ks = 0; ks < 8; ks++) {
            uint32_t ah0[4], ah1[4];
            ldsm4(aBase + M32_AH + ks * 32, ah0);
            ldsm4(aBase + M32_AH + KS + ks * 32, ah1);
#pragma unroll
            for (int g = 0; g < 4; g++) {
                uint32_t bl[4];
                ldsm4t(bBase + (uint32_t)ks * KS + (uint32_t)g * 32, bl);
                mma_bf16(acc[0][g * 2],     ah0, bl);
                mma_bf16(acc[0][g * 2 + 1], ah0, bl + 2);
                mma_bf16(acc[1][g * 2],     ah1, bl);
                mma_bf16(acc[1][g * 2 + 1], ah1, bl + 2);
            }
        }
    }

    // ---- epilogue: bias + tanh + store ----
#pragma unroll
    for (int m = 0; m < 2; m++) {
        int r0 = n0 + wr * 32 + m * 16 + (lane >> 2);
        int r1 = r0 + 8;
#pragma unroll
        for (int nt = 0; nt < 8; nt++) {
            int col = wc * 64 + nt * 8 + (lane & 3) * 2;
            float2 bb = *(const float2*)(b + col);
            if (r0 < NN) {
                float2 o = make_float2(tanhf(acc[m][nt][0] + bb.x),
                                       tanhf(acc[m][nt][1] + bb.y));
                *(float2*)(out + (size_t)r0 * 128 + col) = o;
            }
            if (r1 < NN) {
                float2 o = make_float2(tanhf(acc[m][nt][2] + bb.x),
                                       tanhf(acc[m][nt][3] + bb.y));
                *(float2*)(out + (size_t)r1 * 128 + col) = o;
            }
        }
    }
}

// ==================== HMMA GEMM, M16 warps (hetero mean) ===================
// out = (1/nChunks)*sum_ch tanh(A_ch@W_ch + b_ch); A relation-major slices.
#define SM_AH 0
#define SM_AL 17408
#define SM_W  34816
#define SMEM_MEAN 69632

__global__ void __launch_bounds__(256, 3) tc_gemm_mean(
        int aWhich, int nChunks, int wBase,
        const float* __restrict__ b,
        float* outExt, int outWhich) {
    extern __shared__ unsigned char smem[];
    uint32_t sb = smem_u32(smem);
    int t = threadIdx.x, wid = t >> 5, lane = t & 31;
    int wr = wid & 3, wc = wid >> 2;
    int n0 = blockIdx.x * 64;

    const float* A = selbuf(aWhich, nullptr);
    float* out = selbuf(outWhich, outExt);

    float acc[8][4];
    float fin[8][4];
#pragma unroll
    for (int i = 0; i < 8; i++)
#pragma unroll
        for (int j = 0; j < 4; j++) { acc[i][j] = 0.f; fin[i][j] = 0.f; }

    uint32_t lmrow = (uint32_t)(lane & 15) * 272 + (uint32_t)(lane >> 4) * 16;
    uint32_t aAddrBase = sb + (uint32_t)wr * KS + lmrow;
    uint32_t bAddrBase = sb + SM_W + lmrow + (uint32_t)wc * 128;

    for (int ch = 0; ch < nChunks; ch++) {
        const float* Asrc = A + (size_t)ch * NN * 128;
        const unsigned char* wimg = g_wprep + (size_t)(wBase + ch) * WSTRIDE;

        __syncthreads();
        for (int i = t; i < 2176; i += 256)
            cp_async16(sb + SM_W + (uint32_t)i * 16, wimg + (size_t)i * 16);
        cp_commit();
#pragma unroll
        for (int i = 0; i < 8; i++) {
            int f = t + i * 256;
            int row = f >> 5, c4 = f & 31;
            int rc = n0 + row; if (rc > NN - 1) rc = NN - 1;
            float4 v = *(const float4*)(Asrc + (size_t)rc * 128 + c4 * 4);
            uint32_t h01 = pk_bf16x2(v.x, v.y);
            uint32_t h23 = pk_bf16x2(v.z, v.w);
            uint32_t l01 = pk_bf16x2(v.x - bfbits2f(h01 & 0xFFFFu),
                                     v.y - bfbits2f(h01 >> 16));
            uint32_t l23 = pk_bf16x2(v.z - bfbits2f(h23 & 0xFFFFu),
                                     v.w - bfbits2f(h23 >> 16));
            uint32_t off = (uint32_t)row * 272 + (uint32_t)c4 * 8;
            *(uint2*)(smem + SM_AH + off) = make_uint2(h01, h23);
            *(uint2*)(smem + SM_AL + off) = make_uint2(l01, l23);
        }
        cp_wait0();
        __syncthreads();

#pragma unroll
        for (int ks = 0; ks < 8; ks++) {
            uint32_t ah[4], al[4];
            ldsm4(aAddrBase + SM_AH + ks * 32, ah);
            ldsm4(aAddrBase + SM_AL + ks * 32, al);
#pragma unroll
            for (int g = 0; g < 4; g++) {
                uint32_t bh[4];
                ldsm4t(bAddrBase + (uint32_t)ks * KS + (uint32_t)g * 32, bh);
                mma_bf16(acc[g * 2],     ah, bh);
                mma_bf16(acc[g * 2 + 1], ah, bh + 2);
                mma_bf16(acc[g * 2],     al, bh);
                mma_bf16(acc[g * 2 + 1], al, bh + 2);
            }
        }
        __syncthreads();
        for (int i = t; i < 2176; i += 256)
            cp_async16(sb + SM_W + (uint32_t)i * 16, wimg + WHALF + (size_t)i * 16);
        cp_commit();
        cp_wait0();
        __syncthreads();

#pragma unroll
        for (int ks = 0; ks < 8; ks++) {
            uint32_t ah[4];
            ldsm4(aAddrBase + SM_AH + ks * 32, ah);
#pragma unroll
            for (int g = 0; g < 4; g++) {
                uint32_t bl[4];
                ldsm4t(bAddrBase + (uint32_t)ks * KS + (uint32_t)g * 32, bl);
                mma_bf16(acc[g * 2],     ah, bl);
                mma_bf16(acc[g * 2 + 1], ah, bl + 2);
            }
        }

#pragma unroll
        for (int nt = 0; nt < 8; nt++) {
            int col = wc * 64 + nt * 8 + (lane & 3) * 2;
            float2 bb = *(const float2*)(b + ch * 128 + col);
            fin[nt][0] += tanhf(acc[nt][0] + bb.x);
            fin[nt][1] += tanhf(acc[nt][1] + bb.y);
            fin[nt][2] += tanhf(acc[nt][2] + bb.x);
            fin[nt][3] += tanhf(acc[nt][3] + bb.y);
            acc[nt][0] = acc[nt][1] = acc[nt][2] = acc[nt][3] = 0.f;
        }
    }

    int r0 = n0 + wr * 16 + (lane >> 2);
    int r1 = r0 + 8;
    float s = 1.0f / (float)nChunks;
#pragma unroll
    for (int nt = 0; nt < 8; nt++) {
        int col = wc * 64 + nt * 8 + (lane & 3) * 2;
        if (r0 < NN) {
            float2 o = make_float2(fin[nt][0] * s, fin[nt][1] * s);
            *(float2*)(out + (size_t)r0 * 128 + col) = o;
        }
        if (r1 < NN) {
            float2 o = make_float2(fin[nt][2] * s, fin[nt][3] * s);
            *(float2*)(out + (size_t)r1 * 128 + col) = o;
        }
    }
}

// ---------------------------------------------------------------------------
extern "C" void kernel_launch(void* const* d_in, const int* in_sizes, int n_in,
                              void* d_out, int out_size) {
    const int*   gcn_src1 = (const int*)d_in[0];
    const int*   gcn_dst1 = (const int*)d_in[1];
    const int*   gcn_src2 = (const int*)d_in[2];
    const int*   gcn_dst2 = (const int*)d_in[3];
    const int*   rg_src1  = (const int*)d_in[4];
    const int*   rg_dst1  = (const int*)d_in[5];
    const int*   rg_et1   = (const int*)d_in[6];
    const int*   rg_src2  = (const int*)d_in[7];
    const int*   rg_dst2  = (const int*)d_in[8];
    const int*   rg_et2   = (const int*)d_in[9];
    const int*   het_src1 = (const int*)d_in[10];
    const int*   het_dst1 = (const int*)d_in[11];
    const int*   het_src2 = (const int*)d_in[12];
    const int*   het_dst2 = (const int*)d_in[13];
    const float* emb      = (const float*)d_in[14];
    const float* gcn_W1   = (const float*)d_in[15];
    const float* gcn_b1   = (const float*)d_in[16];
    const float* gcn_W2   = (const float*)d_in[17];
    const float* gcn_b2   = (const float*)d_in[18];
    const float* rg_W1    = (const float*)d_in[19];
    const float* rg_loop1 = (const float*)d_in[20];
    const float* rg_b1    = (const float*)d_in[21];
    const float* rg_W2    = (const float*)d_in[22];
    const float* rg_loop2 = (const float*)d_in[23];
    const float* rg_b2    = (const float*)d_in[24];
    const float* het_W1   = (const float*)d_in[25];
    const float* het_b1   = (const float*)d_in[26];
    const float* het_W2   = (const float*)d_in[27];
    const float* het_b2   = (const float*)d_in[28];

    float* out_hcf = (float*)d_out;
    float* out_hc  = out_hcf + (size_t)NN * D;
    float* out_hs  = out_hcf + (size_t)2 * NN * D;

    cudaFuncSetAttribute(tc_gemm32, cudaFuncAttributeMaxDynamicSharedMemorySize, SMEM_M32);
    cudaFuncSetAttribute(tc_gemm_mean, cudaFuncAttributeMaxDynamicSharedMemorySize, SMEM_MEAN);

    const int ZB = 256, ZG = 2048;
    const int SG = 4096;                // grid-stride scatter blocks
    const int g32 = (NN + 127) / 128;   // 782
    const int g16 = (NN + 63) / 64;     // 1563

    prep_weights<<<28, 128>>>(gcn_W1, gcn_W2, rg_W1, rg_loop1, rg_W2, rg_loop2,
                              het_W1, het_W2);

    // ---- GCN branch ----
    zero_kernel<<<ZG, ZB>>>(2, 0, NN * 32);
    scatter_kernel<<<SG, 256>>>(0, emb, gcn_src1, gcn_dst1, nullptr, 0, 2, EH, 0);
    tc_gemm32<<<g32, 256, SMEM_M32>>>(2, nullptr, 1, 0, 0, 0, nullptr, -1, gcn_b1, nullptr, 1);
    zero_kernel<<<ZG, ZB>>>(2, 0, NN * 32);
    scatter_kernel<<<SG, 256>>>(1, nullptr, gcn_src2, gcn_dst2, nullptr, 0, 2, EH, 0);
    tc_gemm32<<<g32, 256, SMEM_M32>>>(2, nullptr, 1, 1, 0, 0, nullptr, -1, gcn_b2, out_hcf, 0);

    // ---- RGCN branch: per-relation zero+scatter into L2-resident slice ----
    for (int r = 0; r < RRG; r++) {
        zero_kernel<<<ZG, ZB>>>(3, r * NN * 32, NN * 32);
        scatter_kernel<<<SG, 256>>>(0, emb, rg_src1, rg_dst1, rg_et1, r, 3, EH, r * NN);
    }
    tc_gemm32<<<g32, 256, SMEM_M32>>>(3, nullptr, RRG, 2, 1, 0, emb, 10, rg_b1, nullptr, 1);
    for (int r = 0; r < RRG; r++) {
        zero_kernel<<<ZG, ZB>>>(3, r * NN * 32, NN * 32);
        scatter_kernel<<<SG, 256>>>(1, nullptr, rg_src2, rg_dst2, rg_et2, r, 3, EH, r * NN);
    }
    tc_gemm32<<<g32, 256, SMEM_M32>>>(3, nullptr, RRG, 11, 1, 1, nullptr, 19, rg_b2, out_hc, 0);

    // ---- Hetero branch: relations are contiguous edge ranges ----
    for (int r = 0; r < RHET; r++) {
        zero_kernel<<<ZG, ZB>>>(4, r * NN * 32, NN * 32);
        scatter_kernel<<<SG, 256>>>(0, emb, het_src1 + r * EREL, het_dst1 + r * EREL,
                                    nullptr, 0, 4, EREL, r * NN);
    }
    tc_gemm_mean<<<g16, 256, SMEM_MEAN>>>(4, RHET, 20, het_b1, nullptr, 1);
    for (int r = 0; r < RHET; r++) {
        zero_kernel<<<ZG, ZB>>>(4, r * NN * 32, NN * 32);
        scatter_kernel<<<SG, 256>>>(1, nullptr, het_src2 + r * EREL, het_dst2 + r * EREL,
                                    nullptr, 0, 4, EREL, r * NN);
    }
    tc_gemm_mean<<<g16, 256, SMEM_MEAN>>>(4, RHET, 24, het_b2, out_hs, 0);
}

// round 11
// speedup vs baseline: 1.1862x; 1.1862x over previous
#include <cuda_runtime.h>
#include <cuda_bf16.h>
#include <cstdint>

#define NN   100000
#define D    128
#define EH   600000
#define RRG  8
#define RHET 4
#define EREL 150000

// ---- scratch (device globals: no cudaMalloc allowed) ----
__device__ float g_h  [NN * D];                     // 51.2 MB
__device__ float g_agg[NN * D];                     // 51.2 MB
__device__ float g_rb [(size_t)NN * RRG * D];       // 409.6 MB interleaved [n][r][128]
__device__ float g_hb [(size_t)NN * RHET * D];      // 204.8 MB interleaved
// 28 weight matrices, each: bf16 hi block [128k][136] then lo block (272B rows)
#define WROW    272
#define WHALF   34816               // 128 * 272
#define WSTRIDE 69632               // hi + lo
__device__ unsigned char g_wprep[28 * WSTRIDE];

__device__ __forceinline__ float* selbuf(int w, float* dflt) {
    switch (w) {
        case 1: return g_h;
        case 2: return g_agg;
        case 3: return g_rb;
        case 4: return g_hb;
        default: return dflt;
    }
}

// ============================ PTX helpers ==================================
__device__ __forceinline__ uint32_t smem_u32(const void* p) {
    uint32_t a;
    asm("{ .reg .u64 t; cvta.to.shared.u64 t, %1; cvt.u32.u64 %0, t; }" : "=r"(a) : "l"(p));
    return a;
}
__device__ __forceinline__ void ldsm4(uint32_t a, uint32_t* r) {
    asm volatile("ldmatrix.sync.aligned.m8n8.x4.shared.b16 {%0,%1,%2,%3}, [%4];"
                 : "=r"(r[0]), "=r"(r[1]), "=r"(r[2]), "=r"(r[3]) : "r"(a));
}
__device__ __forceinline__ void ldsm4t(uint32_t a, uint32_t* r) {
    asm volatile("ldmatrix.sync.aligned.m8n8.x4.trans.shared.b16 {%0,%1,%2,%3}, [%4];"
                 : "=r"(r[0]), "=r"(r[1]), "=r"(r[2]), "=r"(r[3]) : "r"(a));
}
__device__ __forceinline__ void mma_bf16(float* d, const uint32_t* a, const uint32_t* b) {
    asm volatile(
        "mma.sync.aligned.m16n8k16.row.col.f32.bf16.bf16.f32 "
        "{%0,%1,%2,%3}, {%4,%5,%6,%7}, {%8,%9}, {%0,%1,%2,%3};"
        : "+f"(d[0]), "+f"(d[1]), "+f"(d[2]), "+f"(d[3])
        : "r"(a[0]), "r"(a[1]), "r"(a[2]), "r"(a[3]), "r"(b[0]), "r"(b[1]));
}
__device__ __forceinline__ uint32_t pk_bf16x2(float lo, float hi) {
    uint32_t r;
    asm("cvt.rn.bf16x2.f32 %0, %1, %2;" : "=r"(r) : "f"(hi), "f"(lo));
    return r;
}
__device__ __forceinline__ float bfbits2f(uint32_t b16) { return __uint_as_float(b16 << 16); }
__device__ __forceinline__ void cp_async16(uint32_t saddr, const void* gaddr) {
    asm volatile("cp.async.ca.shared.global [%0], [%1], 16;"
                 :: "r"(saddr), "l"(gaddr) : "memory");
}
__device__ __forceinline__ void cp_commit() {
    asm volatile("cp.async.commit_group;" ::: "memory");
}
__device__ __forceinline__ void cp_wait0() {
    asm volatile("cp.async.wait_group 0;" ::: "memory");
}

// ============================ simple kernels ===============================
__global__ void __launch_bounds__(256) zero_kernel(int which, int n4) {
    float4* p = (float4*)selbuf(which, nullptr);
    int i = blockIdx.x * blockDim.x + threadIdx.x;
    int stride = gridDim.x * blockDim.x;
    float4 z = make_float4(0.f, 0.f, 0.f, 0.f);
    for (; i < n4; i += stride) p[i] = z;
}

// Grid-stride warp-per-edge scatter, single pass, interleaved dest buckets:
// dest row = dst[e]*outR + (et ? et[e] : (relDiv ? e/relDiv : 0)).
__global__ void __launch_bounds__(256) scatter_kernel(
        int xWhich, const float* xExt,
        const int* __restrict__ src, const int* __restrict__ dst,
        const int* __restrict__ et, int relDiv,
        int outR, int outWhich, int E) {
    int nw = (gridDim.x * blockDim.x) >> 5;
    int gw = (blockIdx.x * blockDim.x + threadIdx.x) >> 5;
    int lane = threadIdx.x & 31;
    const float4* x = (const float4*)selbuf(xWhich, (float*)xExt);
    float4* out = (float4*)selbuf(outWhich, nullptr);
    for (int e = gw; e < E; e += nw) {
        int s = src[e];
        int d = dst[e];
        int r = et ? et[e] : (relDiv ? (e / relDiv) : 0);
        size_t dIdx = (size_t)d * outR + (outR > 1 ? r : 0);
        float4 v = x[(size_t)s * 32 + lane];
        float4* o = out + dIdx * 32 + lane;
        asm volatile("red.global.add.v4.f32 [%0], {%1,%2,%3,%4};"
                     :: "l"(o), "f"(v.x), "f"(v.y), "f"(v.z), "f"(v.w)
                     : "memory");
    }
}

// ============================ weight prep ==================================
// Split each fp32 [128k x 128c] matrix into bf16 hi/lo with 272-byte rows
// (136 bf16 stride): 272 mod 128 = 16 -> conflict-free ldmatrix.
__global__ void __launch_bounds__(128) prep_weights(
        const float* gcn_W1, const float* gcn_W2,
        const float* rg_W1, const float* rg_loop1,
        const float* rg_W2, const float* rg_loop2,
        const float* het_W1, const float* het_W2) {
    int blk = blockIdx.x;
    const float* W;
    if      (blk == 0)  W = gcn_W1;
    else if (blk == 1)  W = gcn_W2;
    else if (blk < 10)  W = rg_W1 + (size_t)(blk - 2) * 16384;
    else if (blk == 10) W = rg_loop1;
    else if (blk < 19)  W = rg_W2 + (size_t)(blk - 11) * 16384;
    else if (blk == 19) W = rg_loop2;
    else if (blk < 24)  W = het_W1 + (size_t)(blk - 20) * 16384;
    else                W = het_W2 + (size_t)(blk - 24) * 16384;

    __nv_bfloat16* dh = (__nv_bfloat16*)(g_wprep + (size_t)blk * WSTRIDE);
    __nv_bfloat16* dl = dh + WHALF / 2;
    int c = threadIdx.x;
    for (int k = 0; k < 128; k++) {
        float w = W[k * 128 + c];
        __nv_bfloat16 h = __float2bfloat16(w);
        __nv_bfloat16 l = __float2bfloat16(w - __bfloat162float(h));
        dh[k * 136 + c] = h;
        dl[k * 136 + c] = l;
    }
}

// ==================== HMMA GEMM, M32 warps (sum path) ======================
// 256 threads, 8 warps, CTA tile 128x128, warp tile 32x64.
// Two-phase W in one 34 KB buffer: phase1 WH (ah*bh + al*bh), phase2 WL (ah*bl).
// smem = 2x34816 (A hi/lo) + 34816 (W) -> 2 CTAs/SM. Row stride 272 B
// (272 mod 128 = 16 -> conflict-free ldmatrix and STS).
// out = tanh(sum_ch A_ch @ W_ch (+ X@Wl) + b); A interleaved [n][nChunks*128].
#define M32_AH 0
#define M32_AL 34816
#define M32_W  69632
#define SMEM_M32 104448
#define KS 4352                     // 16 rows * 272

__global__ void __launch_bounds__(256, 2) tc_gemm32(
        int aWhich, const float* aExt, int nChunks, int wBase,
        int xWhich, const float* xExt, int xWIdx,
        const float* __restrict__ b,
        float* outExt, int outWhich) {
    extern __shared__ unsigned char smem[];
    uint32_t sb = smem_u32(smem);
    int t = threadIdx.x, wid = t >> 5, lane = t & 31;
    int wr = wid & 3, wc = wid >> 2;
    int n0 = blockIdx.x * 128;

    const float* A = selbuf(aWhich, (float*)aExt);
    const float* X = (xWIdx >= 0) ? selbuf(xWhich, (float*)xExt) : nullptr;
    float* out = selbuf(outWhich, outExt);

    float acc[2][8][4];
#pragma unroll
    for (int m = 0; m < 2; m++)
#pragma unroll
        for (int i = 0; i < 8; i++)
#pragma unroll
            for (int j = 0; j < 4; j++) acc[m][i][j] = 0.f;

    int ldA = nChunks * 128;
    int tot = nChunks + (X ? 1 : 0);

    uint32_t lmrow = (uint32_t)(lane & 15) * 272 + (uint32_t)(lane >> 4) * 16;
    uint32_t aBase = sb + (uint32_t)wr * (2 * KS) + lmrow;    // + AH|AL + m*KS + ks*32
    uint32_t bBase = sb + M32_W + lmrow + (uint32_t)wc * 128; // + ks*KS + g*32

    for (int ch = 0; ch < tot; ch++) {
        const float* Asrc; int ld, kOff, wIdx;
        if (ch < nChunks) { Asrc = A; ld = ldA; kOff = ch * 128; wIdx = wBase + ch; }
        else              { Asrc = X; ld = 128; kOff = 0;        wIdx = xWIdx; }

        const unsigned char* wimg = g_wprep + (size_t)wIdx * WSTRIDE;

        __syncthreads();
        // ---- async copy WH (34816 B = 2176 x 16B) ----
        for (int i = t; i < 2176; i += 256)
            cp_async16(sb + M32_W + (uint32_t)i * 16, wimg + (size_t)i * 16);
        cp_commit();
        // ---- stage A (128 rows): fp32 -> bf16 hi/lo (overlaps cp.async) ----
#pragma unroll
        for (int i = 0; i < 16; i++) {
            int f = t + i * 256;
            int row = f >> 5, c4 = f & 31;
            int rc = n0 + row; if (rc > NN - 1) rc = NN - 1;
            float4 v = *(const float4*)(Asrc + (size_t)rc * ld + kOff + c4 * 4);
            uint32_t h01 = pk_bf16x2(v.x, v.y);
            uint32_t h23 = pk_bf16x2(v.z, v.w);
            uint32_t l01 = pk_bf16x2(v.x - bfbits2f(h01 & 0xFFFFu),
                                     v.y - bfbits2f(h01 >> 16));
            uint32_t l23 = pk_bf16x2(v.z - bfbits2f(h23 & 0xFFFFu),
                                     v.w - bfbits2f(h23 >> 16));
            uint32_t off = (uint32_t)row * 272 + (uint32_t)c4 * 8;
            *(uint2*)(smem + M32_AH + off) = make_uint2(h01, h23);
            *(uint2*)(smem + M32_AL + off) = make_uint2(l01, l23);
        }
        cp_wait0();
        __syncthreads();

        // ---- phase 1: ah*bh + al*bh ----
#pragma unroll
        for (int ks = 0; ks < 8; ks++) {
            uint32_t ah0[4], ah1[4], al0[4], al1[4];
            ldsm4(aBase + M32_AH + ks * 32, ah0);
            ldsm4(aBase + M32_AH + KS + ks * 32, ah1);
            ldsm4(aBase + M32_AL + ks * 32, al0);
            ldsm4(aBase + M32_AL + KS + ks * 32, al1);
#pragma unroll
            for (int g = 0; g < 4; g++) {
                uint32_t bh[4];
                ldsm4t(bBase + (uint32_t)ks * KS + (uint32_t)g * 32, bh);
                mma_bf16(acc[0][g * 2],     ah0, bh);
                mma_bf16(acc[0][g * 2 + 1], ah0, bh + 2);
                mma_bf16(acc[1][g * 2],     ah1, bh);
                mma_bf16(acc[1][g * 2 + 1], ah1, bh + 2);
                mma_bf16(acc[0][g * 2],     al0, bh);
                mma_bf16(acc[0][g * 2 + 1], al0, bh + 2);
                mma_bf16(acc[1][g * 2],     al1, bh);
                mma_bf16(acc[1][g * 2 + 1], al1, bh + 2);
            }
        }
        __syncthreads();   // done reading WH
        for (int i = t; i < 2176; i += 256)
            cp_async16(sb + M32_W + (uint32_t)i * 16, wimg + WHALF + (size_t)i * 16);
        cp_commit();
        cp_wait0();
        __syncthreads();

        // ---- phase 2: ah*bl ----
#pragma unroll
        for (int ks = 0; ks < 8; ks++) {
            uint32_t ah0[4], ah1[4];
            ldsm4(aBase + M32_AH + ks * 32, ah0);
            ldsm4(aBase + M32_AH + KS + ks * 32, ah1);
#pragma unroll
            for (int g = 0; g < 4; g++) {
                uint32_t bl[4];
                ldsm4t(bBase + (uint32_t)ks * KS + (uint32_t)g * 32, bl);
                mma_bf16(acc[0][g * 2],     ah0, bl);
                mma_bf16(acc[0][g * 2 + 1], ah0, bl + 2);
                mma_bf16(acc[1][g * 2],     ah1, bl);
                mma_bf16(acc[1][g * 2 + 1], ah1, bl + 2);
            }
        }
    }

    // ---- epilogue: bias + tanh + store ----
#pragma unroll
    for (int m = 0; m < 2; m++) {
        int r0 = n0 + wr * 32 + m * 16 + (lane >> 2);
        int r1 = r0 + 8;
#pragma unroll
        for (int nt = 0; nt < 8; nt++) {
            int col = wc * 64 + nt * 8 + (lane & 3) * 2;
            float2 bb = *(const float2*)(b + col);
            if (r0 < NN) {
                float2 o = make_float2(tanhf(acc[m][nt][0] + bb.x),
                                       tanhf(acc[m][nt][1] + bb.y));
                *(float2*)(out + (size_t)r0 * 128 + col) = o;
            }
            if (r1 < NN) {
                float2 o = make_float2(tanhf(acc[m][nt][2] + bb.x),
                                       tanhf(acc[m][nt][3] + bb.y));
                *(float2*)(out + (size_t)r1 * 128 + col) = o;
            }
        }
    }
}

// ==================== HMMA GEMM, M16 warps (hetero mean) ===================
// out = (1/nChunks)*sum_ch tanh(A_ch@W_ch + b_ch); A interleaved buckets.
#define SM_AH 0
#define SM_AL 17408
#define SM_W  34816
#define SMEM_MEAN 69632

__global__ void __launch_bounds__(256, 3) tc_gemm_mean(
        int aWhich, int nChunks, int wBase,
        const float* __restrict__ b,
        float* outExt, int outWhich) {
    extern __shared__ unsigned char smem[];
    uint32_t sb = smem_u32(smem);
    int t = threadIdx.x, wid = t >> 5, lane = t & 31;
    int wr = wid & 3, wc = wid >> 2;
    int n0 = blockIdx.x * 64;

    const float* A = selbuf(aWhich, nullptr);
    float* out = selbuf(outWhich, outExt);

    float acc[8][4];
    float fin[8][4];
#pragma unroll
    for (int i = 0; i < 8; i++)
#pragma unroll
        for (int j = 0; j < 4; j++) { acc[i][j] = 0.f; fin[i][j] = 0.f; }

    int ldA = nChunks * 128;

    uint32_t lmrow = (uint32_t)(lane & 15) * 272 + (uint32_t)(lane >> 4) * 16;
    uint32_t aAddrBase = sb + (uint32_t)wr * KS + lmrow;
    uint32_t bAddrBase = sb + SM_W + lmrow + (uint32_t)wc * 128;

    for (int ch = 0; ch < nChunks; ch++) {
        const unsigned char* wimg = g_wprep + (size_t)(wBase + ch) * WSTRIDE;

        __syncthreads();
        for (int i = t; i < 2176; i += 256)
            cp_async16(sb + SM_W + (uint32_t)i * 16, wimg + (size_t)i * 16);
        cp_commit();
#pragma unroll
        for (int i = 0; i < 8; i++) {
            int f = t + i * 256;
            int row = f >> 5, c4 = f & 31;
            int rc = n0 + row; if (rc > NN - 1) rc = NN - 1;
            float4 v = *(const float4*)(A + (size_t)rc * ldA + ch * 128 + c4 * 4);
            uint32_t h01 = pk_bf16x2(v.x, v.y);
            uint32_t h23 = pk_bf16x2(v.z, v.w);
            uint32_t l01 = pk_bf16x2(v.x - bfbits2f(h01 & 0xFFFFu),
                                     v.y - bfbits2f(h01 >> 16));
            uint32_t l23 = pk_bf16x2(v.z - bfbits2f(h23 & 0xFFFFu),
                                     v.w - bfbits2f(h23 >> 16));
            uint32_t off = (uint32_t)row * 272 + (uint32_t)c4 * 8;
            *(uint2*)(smem + SM_AH + off) = make_uint2(h01, h23);
            *(uint2*)(smem + SM_AL + off) = make_uint2(l01, l23);
        }
        cp_wait0();
        __syncthreads();

#pragma unroll
        for (int ks = 0; ks < 8; ks++) {
            uint32_t ah[4], al[4];
            ldsm4(aAddrBase + SM_AH + ks * 32, ah);
            ldsm4(aAddrBase + SM_AL + ks * 32, al);
#pragma unroll
            for (int g = 0; g < 4; g++) {
                uint32_t bh[4];
                ldsm4t(bAddrBase + (uint32_t)ks * KS + (uint32_t)g * 32, bh);
                mma_bf16(acc[g * 2],     ah, bh);
                mma_bf16(acc[g * 2 + 1], ah, bh + 2);
                mma_bf16(acc[g * 2],     al, bh);
                mma_bf16(acc[g * 2 + 1], al, bh + 2);
            }
        }
        __syncthreads();
        for (int i = t; i < 2176; i += 256)
            cp_async16(sb + SM_W + (uint32_t)i * 16, wimg + WHALF + (size_t)i * 16);
        cp_commit();
        cp_wait0();
        __syncthreads();

#pragma unroll
        for (int ks = 0; ks < 8; ks++) {
            uint32_t ah[4];
            ldsm4(aAddrBase + SM_AH + ks * 32, ah);
#pragma unroll
            for (int g = 0; g < 4; g++) {
                uint32_t bl[4];
                ldsm4t(bAddrBase + (uint32_t)ks * KS + (uint32_t)g * 32, bl);
                mma_bf16(acc[g * 2],     ah, bl);
                mma_bf16(acc[g * 2 + 1], ah, bl + 2);
            }
        }

#pragma unroll
        for (int nt = 0; nt < 8; nt++) {
            int col = wc * 64 + nt * 8 + (lane & 3) * 2;
            float2 bb = *(const float2*)(b + ch * 128 + col);
            fin[nt][0] += tanhf(acc[nt][0] + bb.x);
            fin[nt][1] += tanhf(acc[nt][1] + bb.y);
            fin[nt][2] += tanhf(acc[nt][2] + bb.x);
            fin[nt][3] += tanhf(acc[nt][3] + bb.y);
            acc[nt][0] = acc[nt][1] = acc[nt][2] = acc[nt][3] = 0.f;
        }
    }

    int r0 = n0 + wr * 16 + (lane >> 2);
    int r1 = r0 + 8;
    float s = 1.0f / (float)nChunks;
#pragma unroll
    for (int nt = 0; nt < 8; nt++) {
        int col = wc * 64 + nt * 8 + (lane & 3) * 2;
        if (r0 < NN) {
            float2 o = make_float2(fin[nt][0] * s, fin[nt][1] * s);
            *(float2*)(out + (size_t)r0 * 128 + col) = o;
        }
        if (r1 < NN) {
            float2 o = make_float2(fin[nt][2] * s, fin[nt][3] * s);
            *(float2*)(out + (size_t)r1 * 128 + col) = o;
        }
    }
}

// ---------------------------------------------------------------------------
extern "C" void kernel_launch(void* const* d_in, const int* in_sizes, int n_in,
                              void* d_out, int out_size) {
    const int*   gcn_src1 = (const int*)d_in[0];
    const int*   gcn_dst1 = (const int*)d_in[1];
    const int*   gcn_src2 = (const int*)d_in[2];
    const int*   gcn_dst2 = (const int*)d_in[3];
    const int*   rg_src1  = (const int*)d_in[4];
    const int*   rg_dst1  = (const int*)d_in[5];
    const int*   rg_et1   = (const int*)d_in[6];
    const int*   rg_src2  = (const int*)d_in[7];
    const int*   rg_dst2  = (const int*)d_in[8];
    const int*   rg_et2   = (const int*)d_in[9];
    const int*   het_src1 = (const int*)d_in[10];
    const int*   het_dst1 = (const int*)d_in[11];
    const int*   het_src2 = (const int*)d_in[12];
    const int*   het_dst2 = (const int*)d_in[13];
    const float* emb      = (const float*)d_in[14];
    const float* gcn_W1   = (const float*)d_in[15];
    const float* gcn_b1   = (const float*)d_in[16];
    const float* gcn_W2   = (const float*)d_in[17];
    const float* gcn_b2   = (const float*)d_in[18];
    const float* rg_W1    = (const float*)d_in[19];
    const float* rg_loop1 = (const float*)d_in[20];
    const float* rg_b1    = (const float*)d_in[21];
    const float* rg_W2    = (const float*)d_in[22];
    const float* rg_loop2 = (const float*)d_in[23];
    const float* rg_b2    = (const float*)d_in[24];
    const float* het_W1   = (const float*)d_in[25];
    const float* het_b1   = (const float*)d_in[26];
    const float* het_W2   = (const float*)d_in[27];
    const float* het_b2   = (const float*)d_in[28];

    float* out_hcf = (float*)d_out;
    float* out_hc  = out_hcf + (size_t)NN * D;
    float* out_hs  = out_hcf + (size_t)2 * NN * D;

    cudaFuncSetAttribute(tc_gemm32, cudaFuncAttributeMaxDynamicSharedMemorySize, SMEM_M32);
    cudaFuncSetAttribute(tc_gemm_mean, cudaFuncAttributeMaxDynamicSharedMemorySize, SMEM_MEAN);

    const int ZB = 256, ZG = 2048;
    const int SG = 4096;                // grid-stride scatter blocks
    const int g32 = (NN + 127) / 128;   // 782
    const int g16 = (NN + 63) / 64;     // 1563

    prep_weights<<<28, 128>>>(gcn_W1, gcn_W2, rg_W1, rg_loop1, rg_W2, rg_loop2,
                              het_W1, het_W2);

    // ---- GCN branch ----
    zero_kernel<<<ZG, ZB>>>(2, NN * 32);
    scatter_kernel<<<SG, 256>>>(0, emb, gcn_src1, gcn_dst1, nullptr, 0, 1, 2, EH);
    tc_gemm32<<<g32, 256, SMEM_M32>>>(2, nullptr, 1, 0, 0, nullptr, -1, gcn_b1, nullptr, 1);
    zero_kernel<<<ZG, ZB>>>(2, NN * 32);
    scatter_kernel<<<SG, 256>>>(1, nullptr, gcn_src2, gcn_dst2, nullptr, 0, 1, 2, EH);
    tc_gemm32<<<g32, 256, SMEM_M32>>>(2, nullptr, 1, 1, 0, nullptr, -1, gcn_b2, out_hcf, 0);

    // ---- RGCN branch: single-pass interleaved bucket scatter ----
    zero_kernel<<<ZG, ZB>>>(3, NN * RRG * 32);
    scatter_kernel<<<SG, 256>>>(0, emb, rg_src1, rg_dst1, rg_et1, 0, RRG, 3, EH);
    tc_gemm32<<<g32, 256, SMEM_M32>>>(3, nullptr, RRG, 2, 0, emb, 10, rg_b1, nullptr, 1);
    zero_kernel<<<ZG, ZB>>>(3, NN * RRG * 32);
    scatter_kernel<<<SG, 256>>>(1, nullptr, rg_src2, rg_dst2, rg_et2, 0, RRG, 3, EH);
    tc_gemm32<<<g32, 256, SMEM_M32>>>(3, nullptr, RRG, 11, 1, nullptr, 19, rg_b2, out_hc, 0);

    // ---- Hetero branch ----
    zero_kernel<<<ZG, ZB>>>(4, NN * RHET * 32);
    scatter_kernel<<<SG, 256>>>(0, emb, het_src1, het_dst1, nullptr, EREL, RHET, 4, EH);
    tc_gemm_mean<<<g16, 256, SMEM_MEAN>>>(4, RHET, 20, het_b1, nullptr, 1);
    zero_kernel<<<ZG, ZB>>>(4, NN * RHET * 32);
    scatter_kernel<<<SG, 256>>>(1, nullptr, het_src2, het_dst2, nullptr, EREL, RHET, 4, EH);
    tc_gemm_mean<<<g16, 256, SMEM_MEAN>>>(4, RHET, 24, het_b2, out_hs, 0);
}

// round 12
// speedup vs baseline: 1.3177x; 1.1109x over previous
#include <cuda_runtime.h>
#include <cuda_bf16.h>
#include <cstdint>

#define NN   100000
#define D    128
#define EH   600000
#define RRG  8
#define RHET 4
#define EREL 150000

// ---- scratch (device globals: no cudaMalloc allowed) ----
__device__ float g_h  [NN * D];                     // 51.2 MB  GCN layer-1 temp
__device__ float g_h2 [NN * D];                     // 51.2 MB  RGCN layer-1 temp
__device__ float g_h3 [NN * D];                     // 51.2 MB  hetero layer-1 temp
__device__ float g_agg[NN * D];                     // 51.2 MB  GCN bucket
__device__ float g_rb [(size_t)NN * RRG * D];       // 409.6 MB RGCN buckets [n][r][128]
__device__ float g_hb [(size_t)NN * RHET * D];      // 204.8 MB hetero buckets
// 28 weight matrices, each: bf16 hi block [128k][136] then lo block (272B rows)
#define WROW    272
#define WHALF   34816               // 128 * 272
#define WSTRIDE 69632               // hi + lo
__device__ unsigned char g_wprep[28 * WSTRIDE];

__device__ __forceinline__ float* selbuf(int w, float* dflt) {
    switch (w) {
        case 1: return g_h;
        case 2: return g_agg;
        case 3: return g_rb;
        case 4: return g_hb;
        case 5: return g_h2;
        case 6: return g_h3;
        default: return dflt;
    }
}

// ---- streams/events for captured fork-join (created pre-main, never freed) ----
static cudaStream_t g_s1, g_s2;
static cudaEvent_t  g_eFork, g_eJoin1, g_eJoin2;
static struct StreamInit {
    StreamInit() {
        cudaStreamCreateWithFlags(&g_s1, cudaStreamNonBlocking);
        cudaStreamCreateWithFlags(&g_s2, cudaStreamNonBlocking);
        cudaEventCreateWithFlags(&g_eFork,  cudaEventDisableTiming);
        cudaEventCreateWithFlags(&g_eJoin1, cudaEventDisableTiming);
        cudaEventCreateWithFlags(&g_eJoin2, cudaEventDisableTiming);
    }
} g_streamInit;

// ============================ PTX helpers ==================================
__device__ __forceinline__ uint32_t smem_u32(const void* p) {
    uint32_t a;
    asm("{ .reg .u64 t; cvta.to.shared.u64 t, %1; cvt.u32.u64 %0, t; }" : "=r"(a) : "l"(p));
    return a;
}
__device__ __forceinline__ void ldsm4(uint32_t a, uint32_t* r) {
    asm volatile("ldmatrix.sync.aligned.m8n8.x4.shared.b16 {%0,%1,%2,%3}, [%4];"
                 : "=r"(r[0]), "=r"(r[1]), "=r"(r[2]), "=r"(r[3]) : "r"(a));
}
__device__ __forceinline__ void ldsm4t(uint32_t a, uint32_t* r) {
    asm volatile("ldmatrix.sync.aligned.m8n8.x4.trans.shared.b16 {%0,%1,%2,%3}, [%4];"
                 : "=r"(r[0]), "=r"(r[1]), "=r"(r[2]), "=r"(r[3]) : "r"(a));
}
__device__ __forceinline__ void mma_bf16(float* d, const uint32_t* a, const uint32_t* b) {
    asm volatile(
        "mma.sync.aligned.m16n8k16.row.col.f32.bf16.bf16.f32 "
        "{%0,%1,%2,%3}, {%4,%5,%6,%7}, {%8,%9}, {%0,%1,%2,%3};"
        : "+f"(d[0]), "+f"(d[1]), "+f"(d[2]), "+f"(d[3])
        : "r"(a[0]), "r"(a[1]), "r"(a[2]), "r"(a[3]), "r"(b[0]), "r"(b[1]));
}
__device__ __forceinline__ uint32_t pk_bf16x2(float lo, float hi) {
    uint32_t r;
    asm("cvt.rn.bf16x2.f32 %0, %1, %2;" : "=r"(r) : "f"(hi), "f"(lo));
    return r;
}
__device__ __forceinline__ float bfbits2f(uint32_t b16) { return __uint_as_float(b16 << 16); }
__device__ __forceinline__ void cp_async16(uint32_t saddr, const void* gaddr) {
    asm volatile("cp.async.ca.shared.global [%0], [%1], 16;"
                 :: "r"(saddr), "l"(gaddr) : "memory");
}
__device__ __forceinline__ void cp_commit() {
    asm volatile("cp.async.commit_group;" ::: "memory");
}
__device__ __forceinline__ void cp_wait0() {
    asm volatile("cp.async.wait_group 0;" ::: "memory");
}

// ============================ simple kernels ===============================
__global__ void __launch_bounds__(256) zero_kernel(int which, int n4) {
    float4* p = (float4*)selbuf(which, nullptr);
    int i = blockIdx.x * blockDim.x + threadIdx.x;
    int stride = gridDim.x * blockDim.x;
    float4 z = make_float4(0.f, 0.f, 0.f, 0.f);
    for (; i < n4; i += stride) p[i] = z;
}

// Grid-stride warp-per-edge scatter, single pass, interleaved dest buckets:
// dest row = dst[e]*outR + (et ? et[e] : (relDiv ? e/relDiv : 0)).
__global__ void __launch_bounds__(256) scatter_kernel(
        int xWhich, const float* xExt,
        const int* __restrict__ src, const int* __restrict__ dst,
        const int* __restrict__ et, int relDiv,
        int outR, int outWhich, int E) {
    int nw = (gridDim.x * blockDim.x) >> 5;
    int gw = (blockIdx.x * blockDim.x + threadIdx.x) >> 5;
    int lane = threadIdx.x & 31;
    const float4* x = (const float4*)selbuf(xWhich, (float*)xExt);
    float4* out = (float4*)selbuf(outWhich, nullptr);
    for (int e = gw; e < E; e += nw) {
        int s = src[e];
        int d = dst[e];
        int r = et ? et[e] : (relDiv ? (e / relDiv) : 0);
        size_t dIdx = (size_t)d * outR + (outR > 1 ? r : 0);
        float4 v = x[(size_t)s * 32 + lane];
        float4* o = out + dIdx * 32 + lane;
        asm volatile("red.global.add.v4.f32 [%0], {%1,%2,%3,%4};"
                     :: "l"(o), "f"(v.x), "f"(v.y), "f"(v.z), "f"(v.w)
                     : "memory");
    }
}

// ============================ weight prep ==================================
// Split each fp32 [128k x 128c] matrix into bf16 hi/lo with 272-byte rows
// (136 bf16 stride): 272 mod 128 = 16 -> conflict-free ldmatrix.
__global__ void __launch_bounds__(128) prep_weights(
        const float* gcn_W1, const float* gcn_W2,
        const float* rg_W1, const float* rg_loop1,
        const float* rg_W2, const float* rg_loop2,
        const float* het_W1, const float* het_W2) {
    int blk = blockIdx.x;
    const float* W;
    if      (blk == 0)  W = gcn_W1;
    else if (blk == 1)  W = gcn_W2;
    else if (blk < 10)  W = rg_W1 + (size_t)(blk - 2) * 16384;
    else if (blk == 10) W = rg_loop1;
    else if (blk < 19)  W = rg_W2 + (size_t)(blk - 11) * 16384;
    else if (blk == 19) W = rg_loop2;
    else if (blk < 24)  W = het_W1 + (size_t)(blk - 20) * 16384;
    else                W = het_W2 + (size_t)(blk - 24) * 16384;

    __nv_bfloat16* dh = (__nv_bfloat16*)(g_wprep + (size_t)blk * WSTRIDE);
    __nv_bfloat16* dl = dh + WHALF / 2;
    int c = threadIdx.x;
    for (int k = 0; k < 128; k++) {
        float w = W[k * 128 + c];
        __nv_bfloat16 h = __float2bfloat16(w);
        __nv_bfloat16 l = __float2bfloat16(w - __bfloat162float(h));
        dh[k * 136 + c] = h;
        dl[k * 136 + c] = l;
    }
}

// ==================== HMMA GEMM, M32 warps (sum path) ======================
// 256 threads, 8 warps, CTA tile 128x128, warp tile 32x64.
// Two-phase W in one 34 KB buffer: phase1 WH (ah*bh + al*bh), phase2 WL (ah*bl).
// smem = 2x34816 (A hi/lo) + 34816 (W) -> 2 CTAs/SM. Row stride 272 B.
// out = tanh(sum_ch A_ch @ W_ch (+ X@Wl) + b); A interleaved [n][nChunks*128].
#define M32_AH 0
#define M32_AL 34816
#define M32_W  69632
#define SMEM_M32 104448
#define KS 4352                     // 16 rows * 272

__global__ void __launch_bounds__(256, 2) tc_gemm32(
        int aWhich, const float* aExt, int nChunks, int wBase,
        int xWhich, const float* xExt, int xWIdx,
        const float* __restrict__ b,
        float* outExt, int outWhich) {
    extern __shared__ unsigned char smem[];
    uint32_t sb = smem_u32(smem);
    int t = threadIdx.x, wid = t >> 5, lane = t & 31;
    int wr = wid & 3, wc = wid >> 2;
    int n0 = blockIdx.x * 128;

    const float* A = selbuf(aWhich, (float*)aExt);
    const float* X = (xWIdx >= 0) ? selbuf(xWhich, (float*)xExt) : nullptr;
    float* out = selbuf(outWhich, outExt);

    float acc[2][8][4];
#pragma unroll
    for (int m = 0; m < 2; m++)
#pragma unroll
        for (int i = 0; i < 8; i++)
#pragma unroll
            for (int j = 0; j < 4; j++) acc[m][i][j] = 0.f;

    int ldA = nChunks * 128;
    int tot = nChunks + (X ? 1 : 0);

    uint32_t lmrow = (uint32_t)(lane & 15) * 272 + (uint32_t)(lane >> 4) * 16;
    uint32_t aBase = sb + (uint32_t)wr * (2 * KS) + lmrow;    // + AH|AL + m*KS + ks*32
    uint32_t bBase = sb + M32_W + lmrow + (uint32_t)wc * 128; // + ks*KS + g*32

    for (int ch = 0; ch < tot; ch++) {
        const float* Asrc; int ld, kOff, wIdx;
        if (ch < nChunks) { Asrc = A; ld = ldA; kOff = ch * 128; wIdx = wBase + ch; }
        else              { Asrc = X; ld = 128; kOff = 0;        wIdx = xWIdx; }

        const unsigned char* wimg = g_wprep + (size_t)wIdx * WSTRIDE;

        __syncthreads();
        // ---- async copy WH (34816 B = 2176 x 16B) ----
        for (int i = t; i < 2176; i += 256)
            cp_async16(sb + M32_W + (uint32_t)i * 16, wimg + (size_t)i * 16);
        cp_commit();
        // ---- stage A (128 rows): fp32 -> bf16 hi/lo (overlaps cp.async) ----
#pragma unroll
        for (int i = 0; i < 16; i++) {
            int f = t + i * 256;
            int row = f >> 5, c4 = f & 31;
            int rc = n0 + row; if (rc > NN - 1) rc = NN - 1;
            float4 v = *(const float4*)(Asrc + (size_t)rc * ld + kOff + c4 * 4);
            uint32_t h01 = pk_bf16x2(v.x, v.y);
            uint32_t h23 = pk_bf16x2(v.z, v.w);
            uint32_t l01 = pk_bf16x2(v.x - bfbits2f(h01 & 0xFFFFu),
                                     v.y - bfbits2f(h01 >> 16));
            uint32_t l23 = pk_bf16x2(v.z - bfbits2f(h23 & 0xFFFFu),
                                     v.w - bfbits2f(h23 >> 16));
            uint32_t off = (uint32_t)row * 272 + (uint32_t)c4 * 8;
            *(uint2*)(smem + M32_AH + off) = make_uint2(h01, h23);
            *(uint2*)(smem + M32_AL + off) = make_uint2(l01, l23);
        }
        cp_wait0();
        __syncthreads();

        // ---- phase 1: ah*bh + al*bh ----
#pragma unroll
        for (int ks = 0; ks < 8; ks++) {
            uint32_t ah0[4], ah1[4], al0[4], al1[4];
            ldsm4(aBase + M32_AH + ks * 32, ah0);
            ldsm4(aBase + M32_AH + KS + ks * 32, ah1);
            ldsm4(aBase + M32_AL + ks * 32, al0);
            ldsm4(aBase + M32_AL + KS + ks * 32, al1);
#pragma unroll
            for (int g = 0; g < 4; g++) {
                uint32_t bh[4];
                ldsm4t(bBase + (uint32_t)ks * KS + (uint32_t)g * 32, bh);
                mma_bf16(acc[0][g * 2],     ah0, bh);
                mma_bf16(acc[0][g * 2 + 1], ah0, bh + 2);
                mma_bf16(acc[1][g * 2],     ah1, bh);
                mma_bf16(acc[1][g * 2 + 1], ah1, bh + 2);
                mma_bf16(acc[0][g * 2],     al0, bh);
                mma_bf16(acc[0][g * 2 + 1], al0, bh + 2);
                mma_bf16(acc[1][g * 2],     al1, bh);
                mma_bf16(acc[1][g * 2 + 1], al1, bh + 2);
            }
        }
        __syncthreads();   // done reading WH
        for (int i = t; i < 2176; i += 256)
            cp_async16(sb + M32_W + (uint32_t)i * 16, wimg + WHALF + (size_t)i * 16);
        cp_commit();
        cp_wait0();
        __syncthreads();

        // ---- phase 2: ah*bl ----
#pragma unroll
        for (int ks = 0; ks < 8; ks++) {
            uint32_t ah0[4], ah1[4];
            ldsm4(aBase + M32_AH + ks * 32, ah0);
            ldsm4(aBase + M32_AH + KS + ks * 32, ah1);
#pragma unroll
            for (int g = 0; g < 4; g++) {
                uint32_t bl[4];
                ldsm4t(bBase + (uint32_t)ks * KS + (uint32_t)g * 32, bl);
                mma_bf16(acc[0][g * 2],     ah0, bl);
                mma_bf16(acc[0][g * 2 + 1], ah0, bl + 2);
                mma_bf16(acc[1][g * 2],     ah1, bl);
                mma_bf16(acc[1][g * 2 + 1], ah1, bl + 2);
            }
        }
    }

    // ---- epilogue: bias + tanh + store ----
#pragma unroll
    for (int m = 0; m < 2; m++) {
        int r0 = n0 + wr * 32 + m * 16 + (lane >> 2);
        int r1 = r0 + 8;
#pragma unroll
        for (int nt = 0; nt < 8; nt++) {
            int col = wc * 64 + nt * 8 + (lane & 3) * 2;
            float2 bb = *(const float2*)(b + col);
            if (r0 < NN) {
                float2 o = make_float2(tanhf(acc[m][nt][0] + bb.x),
                                       tanhf(acc[m][nt][1] + bb.y));
                *(float2*)(out + (size_t)r0 * 128 + col) = o;
            }
            if (r1 < NN) {
                float2 o = make_float2(tanhf(acc[m][nt][2] + bb.x),
                                       tanhf(acc[m][nt][3] + bb.y));
                *(float2*)(out + (size_t)r1 * 128 + col) = o;
            }
        }
    }
}

// ==================== HMMA GEMM, M16 warps (hetero mean) ===================
// out = (1/nChunks)*sum_ch tanh(A_ch@W_ch + b_ch); A interleaved buckets.
#define SM_AH 0
#define SM_AL 17408
#define SM_W  34816
#define SMEM_MEAN 69632

__global__ void __launch_bounds__(256, 3) tc_gemm_mean(
        int aWhich, int nChunks, int wBase,
        const float* __restrict__ b,
        float* outExt, int outWhich) {
    extern __shared__ unsigned char smem[];
    uint32_t sb = smem_u32(smem);
    int t = threadIdx.x, wid = t >> 5, lane = t & 31;
    int wr = wid & 3, wc = wid >> 2;
    int n0 = blockIdx.x * 64;

    const float* A = selbuf(aWhich, nullptr);
    float* out = selbuf(outWhich, outExt);

    float acc[8][4];
    float fin[8][4];
#pragma unroll
    for (int i = 0; i < 8; i++)
#pragma unroll
        for (int j = 0; j < 4; j++) { acc[i][j] = 0.f; fin[i][j] = 0.f; }

    int ldA = nChunks * 128;

    uint32_t lmrow = (uint32_t)(lane & 15) * 272 + (uint32_t)(lane >> 4) * 16;
    uint32_t aAddrBase = sb + (uint32_t)wr * KS + lmrow;
    uint32_t bAddrBase = sb + SM_W + lmrow + (uint32_t)wc * 128;

    for (int ch = 0; ch < nChunks; ch++) {
        const unsigned char* wimg = g_wprep + (size_t)(wBase + ch) * WSTRIDE;

        __syncthreads();
        for (int i = t; i < 2176; i += 256)
            cp_async16(sb + SM_W + (uint32_t)i * 16, wimg + (size_t)i * 16);
        cp_commit();
#pragma unroll
        for (int i = 0; i < 8; i++) {
            int f = t + i * 256;
            int row = f >> 5, c4 = f & 31;
            int rc = n0 + row; if (rc > NN - 1) rc = NN - 1;
            float4 v = *(const float4*)(A + (size_t)rc * ldA + ch * 128 + c4 * 4);
            uint32_t h01 = pk_bf16x2(v.x, v.y);
            uint32_t h23 = pk_bf16x2(v.z, v.w);
            uint32_t l01 = pk_bf16x2(v.x - bfbits2f(h01 & 0xFFFFu),
                                     v.y - bfbits2f(h01 >> 16));
            uint32_t l23 = pk_bf16x2(v.z - bfbits2f(h23 & 0xFFFFu),
                                     v.w - bfbits2f(h23 >> 16));
            uint32_t off = (uint32_t)row * 272 + (uint32_t)c4 * 8;
            *(uint2*)(smem + SM_AH + off) = make_uint2(h01, h23);
            *(uint2*)(smem + SM_AL + off) = make_uint2(l01, l23);
        }
        cp_wait0();
        __syncthreads();

#pragma unroll
        for (int ks = 0; ks < 8; ks++) {
            uint32_t ah[4], al[4];
            ldsm4(aAddrBase + SM_AH + ks * 32, ah);
            ldsm4(aAddrBase + SM_AL + ks * 32, al);
#pragma unroll
            for (int g = 0; g < 4; g++) {
                uint32_t bh[4];
                ldsm4t(bAddrBase + (uint32_t)ks * KS + (uint32_t)g * 32, bh);
                mma_bf16(acc[g * 2],     ah, bh);
                mma_bf16(acc[g * 2 + 1], ah, bh + 2);
                mma_bf16(acc[g * 2],     al, bh);
                mma_bf16(acc[g * 2 + 1], al, bh + 2);
            }
        }
        __syncthreads();
        for (int i = t; i < 2176; i += 256)
            cp_async16(sb + SM_W + (uint32_t)i * 16, wimg + WHALF + (size_t)i * 16);
        cp_commit();
        cp_wait0();
        __syncthreads();

#pragma unroll
        for (int ks = 0; ks < 8; ks++) {
            uint32_t ah[4];
            ldsm4(aAddrBase + SM_AH + ks * 32, ah);
#pragma unroll
            for (int g = 0; g < 4; g++) {
                uint32_t bl[4];
                ldsm4t(bAddrBase + (uint32_t)ks * KS + (uint32_t)g * 32, bl);
                mma_bf16(acc[g * 2],     ah, bl);
                mma_bf16(acc[g * 2 + 1], ah, bl + 2);
            }
        }

#pragma unroll
        for (int nt = 0; nt < 8; nt++) {
            int col = wc * 64 + nt * 8 + (lane & 3) * 2;
            float2 bb = *(const float2*)(b + ch * 128 + col);
            fin[nt][0] += tanhf(acc[nt][0] + bb.x);
            fin[nt][1] += tanhf(acc[nt][1] + bb.y);
            fin[nt][2] += tanhf(acc[nt][2] + bb.x);
            fin[nt][3] += tanhf(acc[nt][3] + bb.y);
            acc[nt][0] = acc[nt][1] = acc[nt][2] = acc[nt][3] = 0.f;
        }
    }

    int r0 = n0 + wr * 16 + (lane >> 2);
    int r1 = r0 + 8;
    float s = 1.0f / (float)nChunks;
#pragma unroll
    for (int nt = 0; nt < 8; nt++) {
        int col = wc * 64 + nt * 8 + (lane & 3) * 2;
        if (r0 < NN) {
            float2 o = make_float2(fin[nt][0] * s, fin[nt][1] * s);
            *(float2*)(out + (size_t)r0 * 128 + col) = o;
        }
        if (r1 < NN) {
            float2 o = make_float2(fin[nt][2] * s, fin[nt][3] * s);
            *(float2*)(out + (size_t)r1 * 128 + col) = o;
        }
    }
}

// ---------------------------------------------------------------------------
extern "C" void kernel_launch(void* const* d_in, const int* in_sizes, int n_in,
                              void* d_out, int out_size) {
    const int*   gcn_src1 = (const int*)d_in[0];
    const int*   gcn_dst1 = (const int*)d_in[1];
    const int*   gcn_src2 = (const int*)d_in[2];
    const int*   gcn_dst2 = (const int*)d_in[3];
    const int*   rg_src1  = (const int*)d_in[4];
    const int*   rg_dst1  = (const int*)d_in[5];
    const int*   rg_et1   = (const int*)d_in[6];
    const int*   rg_src2  = (const int*)d_in[7];
    const int*   rg_dst2  = (const int*)d_in[8];
    const int*   rg_et2   = (const int*)d_in[9];
    const int*   het_src1 = (const int*)d_in[10];
    const int*   het_dst1 = (const int*)d_in[11];
    const int*   het_src2 = (const int*)d_in[12];
    const int*   het_dst2 = (const int*)d_in[13];
    const float* emb      = (const float*)d_in[14];
    const float* gcn_W1   = (const float*)d_in[15];
    const float* gcn_b1   = (const float*)d_in[16];
    const float* gcn_W2   = (const float*)d_in[17];
    const float* gcn_b2   = (const float*)d_in[18];
    const float* rg_W1    = (const float*)d_in[19];
    const float* rg_loop1 = (const float*)d_in[20];
    const float* rg_b1    = (const float*)d_in[21];
    const float* rg_W2    = (const float*)d_in[22];
    const float* rg_loop2 = (const float*)d_in[23];
    const float* rg_b2    = (const float*)d_in[24];
    const float* het_W1   = (const float*)d_in[25];
    const float* het_b1   = (const float*)d_in[26];
    const float* het_W2   = (const float*)d_in[27];
    const float* het_b2   = (const float*)d_in[28];

    float* out_hcf = (float*)d_out;
    float* out_hc  = out_hcf + (size_t)NN * D;
    float* out_hs  = out_hcf + (size_t)2 * NN * D;

    cudaFuncSetAttribute(tc_gemm32, cudaFuncAttributeMaxDynamicSharedMemorySize, SMEM_M32);
    cudaFuncSetAttribute(tc_gemm_mean, cudaFuncAttributeMaxDynamicSharedMemorySize, SMEM_MEAN);

    const int ZB = 256, ZG = 2048;
    const int SG = 4096;                // grid-stride scatter blocks
    const int g32 = (NN + 127) / 128;   // 782
    const int g16 = (NN + 63) / 64;     // 1563

    // ---- prep on main stream, then fork ----
    prep_weights<<<28, 128>>>(gcn_W1, gcn_W2, rg_W1, rg_loop1, rg_W2, rg_loop2,
                              het_W1, het_W2);
    cudaEventRecord(g_eFork, 0);
    cudaStreamWaitEvent(g_s1, g_eFork, 0);
    cudaStreamWaitEvent(g_s2, g_eFork, 0);

    // ---- GCN branch (main stream): bucket=g_agg(2), temp=g_h(1) ----
    zero_kernel<<<ZG, ZB>>>(2, NN * 32);
    scatter_kernel<<<SG, 256>>>(0, emb, gcn_src1, gcn_dst1, nullptr, 0, 1, 2, EH);
    tc_gemm32<<<g32, 256, SMEM_M32>>>(2, nullptr, 1, 0, 0, nullptr, -1, gcn_b1, nullptr, 1);
    zero_kernel<<<ZG, ZB>>>(2, NN * 32);
    scatter_kernel<<<SG, 256>>>(1, nullptr, gcn_src2, gcn_dst2, nullptr, 0, 1, 2, EH);
    tc_gemm32<<<g32, 256, SMEM_M32>>>(2, nullptr, 1, 1, 0, nullptr, -1, gcn_b2, out_hcf, 0);

    // ---- RGCN branch (s1): buckets=g_rb(3), temp=g_h2(5) ----
    zero_kernel<<<ZG, ZB, 0, g_s1>>>(3, NN * RRG * 32);
    scatter_kernel<<<SG, 256, 0, g_s1>>>(0, emb, rg_src1, rg_dst1, rg_et1, 0, RRG, 3, EH);
    tc_gemm32<<<g32, 256, SMEM_M32, g_s1>>>(3, nullptr, RRG, 2, 0, emb, 10, rg_b1, nullptr, 5);
    zero_kernel<<<ZG, ZB, 0, g_s1>>>(3, NN * RRG * 32);
    scatter_kernel<<<SG, 256, 0, g_s1>>>(5, nullptr, rg_src2, rg_dst2, rg_et2, 0, RRG, 3, EH);
    tc_gemm32<<<g32, 256, SMEM_M32, g_s1>>>(3, nullptr, RRG, 11, 5, nullptr, 19, rg_b2, out_hc, 0);
    cudaEventRecord(g_eJoin1, g_s1);

    // ---- Hetero branch (s2): buckets=g_hb(4), temp=g_h3(6) ----
    zero_kernel<<<ZG, ZB, 0, g_s2>>>(4, NN * RHET * 32);
    scatter_kernel<<<SG, 256, 0, g_s2>>>(0, emb, het_src1, het_dst1, nullptr, EREL, RHET, 4, EH);
    tc_gemm_mean<<<g16, 256, SMEM_MEAN, g_s2>>>(4, RHET, 20, het_b1, nullptr, 6);
    zero_kernel<<<ZG, ZB, 0, g_s2>>>(4, NN * RHET * 32);
    scatter_kernel<<<SG, 256, 0, g_s2>>>(6, nullptr, het_src2, het_dst2, nullptr, EREL, RHET, 4, EH);
    tc_gemm_mean<<<g16, 256, SMEM_MEAN, g_s2>>>(4, RHET, 24, het_b2, out_hs, 0);
    cudaEventRecord(g_eJoin2, g_s2);

    // ---- join back to main stream ----
    cudaStreamWaitEvent(0, g_eJoin1, 0);
    cudaStreamWaitEvent(0, g_eJoin2, 0);
}

// round 13
// speedup vs baseline: 1.3797x; 1.0470x over previous
#include <cuda_runtime.h>
#include <cuda_bf16.h>
#include <cstdint>

#define NN   100000
#define D    128
#define EH   600000
#define RRG  8
#define RHET 4
#define EREL 150000

// ---- scratch (device globals: no cudaMalloc allowed) ----
__device__ float g_h  [NN * D];                     // 51.2 MB  GCN layer-1 temp
__device__ float g_h2 [NN * D];                     // 51.2 MB  RGCN layer-1 temp
__device__ float g_h3 [NN * D];                     // 51.2 MB  hetero layer-1 temp
__device__ float g_agg [NN * D];                    // 51.2 MB  GCN bucket
__device__ float g_agg2[NN * D];                    // 51.2 MB  RGCN agg (L2-resident)
__device__ float g_rb [(size_t)NN * RRG * D];       // 409.6 MB RGCN H, relation-major [r][n][128]
__device__ float g_hb [(size_t)NN * RHET * D];      // 204.8 MB hetero buckets [n][r][128]
// 28 weight matrices, each: bf16 hi block [128k][136] then lo block (272B rows)
#define WROW    272
#define WHALF   34816               // 128 * 272
#define WSTRIDE 69632               // hi + lo
__device__ unsigned char g_wprep[28 * WSTRIDE];

__device__ __forceinline__ float* selbuf(int w, float* dflt) {
    switch (w) {
        case 1: return g_h;
        case 2: return g_agg;
        case 3: return g_rb;
        case 4: return g_hb;
        case 5: return g_h2;
        case 6: return g_h3;
        case 7: return g_agg2;
        default: return dflt;
    }
}

// ---- streams/events for captured fork-join (created pre-main, never freed) ----
static cudaStream_t g_s1, g_s2;
static cudaEvent_t  g_eFork, g_eJoin1, g_eJoin2;
static struct StreamInit {
    StreamInit() {
        cudaStreamCreateWithFlags(&g_s1, cudaStreamNonBlocking);
        cudaStreamCreateWithFlags(&g_s2, cudaStreamNonBlocking);
        cudaEventCreateWithFlags(&g_eFork,  cudaEventDisableTiming);
        cudaEventCreateWithFlags(&g_eJoin1, cudaEventDisableTiming);
        cudaEventCreateWithFlags(&g_eJoin2, cudaEventDisableTiming);
    }
} g_streamInit;

// ============================ PTX helpers ==================================
__device__ __forceinline__ uint32_t smem_u32(const void* p) {
    uint32_t a;
    asm("{ .reg .u64 t; cvta.to.shared.u64 t, %1; cvt.u32.u64 %0, t; }" : "=r"(a) : "l"(p));
    return a;
}
__device__ __forceinline__ void ldsm4(uint32_t a, uint32_t* r) {
    asm volatile("ldmatrix.sync.aligned.m8n8.x4.shared.b16 {%0,%1,%2,%3}, [%4];"
                 : "=r"(r[0]), "=r"(r[1]), "=r"(r[2]), "=r"(r[3]) : "r"(a));
}
__device__ __forceinline__ void ldsm4t(uint32_t a, uint32_t* r) {
    asm volatile("ldmatrix.sync.aligned.m8n8.x4.trans.shared.b16 {%0,%1,%2,%3}, [%4];"
                 : "=r"(r[0]), "=r"(r[1]), "=r"(r[2]), "=r"(r[3]) : "r"(a));
}
__device__ __forceinline__ void mma_bf16(float* d, const uint32_t* a, const uint32_t* b) {
    asm volatile(
        "mma.sync.aligned.m16n8k16.row.col.f32.bf16.bf16.f32 "
        "{%0,%1,%2,%3}, {%4,%5,%6,%7}, {%8,%9}, {%0,%1,%2,%3};"
        : "+f"(d[0]), "+f"(d[1]), "+f"(d[2]), "+f"(d[3])
        : "r"(a[0]), "r"(a[1]), "r"(a[2]), "r"(a[3]), "r"(b[0]), "r"(b[1]));
}
__device__ __forceinline__ uint32_t pk_bf16x2(float lo, float hi) {
    uint32_t r;
    asm("cvt.rn.bf16x2.f32 %0, %1, %2;" : "=r"(r) : "f"(hi), "f"(lo));
    return r;
}
__device__ __forceinline__ float bfbits2f(uint32_t b16) { return __uint_as_float(b16 << 16); }
__device__ __forceinline__ void cp_async16(uint32_t saddr, const void* gaddr) {
    asm volatile("cp.async.ca.shared.global [%0], [%1], 16;"
                 :: "r"(saddr), "l"(gaddr) : "memory");
}
__device__ __forceinline__ void cp_commit() {
    asm volatile("cp.async.commit_group;" ::: "memory");
}
__device__ __forceinline__ void cp_wait0() {
    asm volatile("cp.async.wait_group 0;" ::: "memory");
}

// ============================ simple kernels ===============================
__global__ void __launch_bounds__(256) zero_kernel(int which, int n4) {
    float4* p = (float4*)selbuf(which, nullptr);
    int i = blockIdx.x * blockDim.x + threadIdx.x;
    int stride = gridDim.x * blockDim.x;
    float4 z = make_float4(0.f, 0.f, 0.f, 0.f);
    for (; i < n4; i += stride) p[i] = z;
}

// Grid-stride warp-per-edge scatter.
//   source row = srcRelMajor ? (rel*NN + src[e]) : src[e]
//   dest   row = dst[e]*outR + (outR>1 ? rel : 0)
//   rel = et ? et[e] : (relDiv ? e/relDiv : 0)
__global__ void __launch_bounds__(256) scatter_kernel(
        int xWhich, const float* xExt,
        const int* __restrict__ src, const int* __restrict__ dst,
        const int* __restrict__ et, int relDiv, int srcRelMajor,
        int outR, int outWhich, int E) {
    int nw = (gridDim.x * blockDim.x) >> 5;
    int gw = (blockIdx.x * blockDim.x + threadIdx.x) >> 5;
    int lane = threadIdx.x & 31;
    const float4* x = (const float4*)selbuf(xWhich, (float*)xExt);
    float4* out = (float4*)selbuf(outWhich, nullptr);
    for (int e = gw; e < E; e += nw) {
        int s = src[e];
        int d = dst[e];
        int r = et ? et[e] : (relDiv ? (e / relDiv) : 0);
        size_t sIdx = srcRelMajor ? ((size_t)r * NN + s) : (size_t)s;
        size_t dIdx = (size_t)d * outR + (outR > 1 ? r : 0);
        float4 v = x[sIdx * 32 + lane];
        float4* o = out + dIdx * 32 + lane;
        asm volatile("red.global.add.v4.f32 [%0], {%1,%2,%3,%4};"
                     :: "l"(o), "f"(v.x), "f"(v.y), "f"(v.z), "f"(v.w)
                     : "memory");
    }
}

// ============================ weight prep ==================================
// Split each fp32 [128k x 128c] matrix into bf16 hi/lo with 272-byte rows
// (136 bf16 stride): 272 mod 128 = 16 -> conflict-free ldmatrix.
__global__ void __launch_bounds__(128) prep_weights(
        const float* gcn_W1, const float* gcn_W2,
        const float* rg_W1, const float* rg_loop1,
        const float* rg_W2, const float* rg_loop2,
        const float* het_W1, const float* het_W2) {
    int blk = blockIdx.x;
    const float* W;
    if      (blk == 0)  W = gcn_W1;
    else if (blk == 1)  W = gcn_W2;
    else if (blk < 10)  W = rg_W1 + (size_t)(blk - 2) * 16384;
    else if (blk == 10) W = rg_loop1;
    else if (blk < 19)  W = rg_W2 + (size_t)(blk - 11) * 16384;
    else if (blk == 19) W = rg_loop2;
    else if (blk < 24)  W = het_W1 + (size_t)(blk - 20) * 16384;
    else                W = het_W2 + (size_t)(blk - 24) * 16384;

    __nv_bfloat16* dh = (__nv_bfloat16*)(g_wprep + (size_t)blk * WSTRIDE);
    __nv_bfloat16* dl = dh + WHALF / 2;
    int c = threadIdx.x;
    for (int k = 0; k < 128; k++) {
        float w = W[k * 128 + c];
        __nv_bfloat16 h = __float2bfloat16(w);
        __nv_bfloat16 l = __float2bfloat16(w - __bfloat162float(h));
        dh[k * 136 + c] = h;
        dl[k * 136 + c] = l;
    }
}

// =============== shared GEMM building blocks (M32 layout) ==================
#define M32_AH 0
#define M32_AL 34816
#define M32_W  69632
#define SMEM_M32 104448
#define KS 4352                     // 16 rows * 272

// Stage 128 rows of A (fp32) as bf16 hi/lo into smem (row stride 272).
__device__ __forceinline__ void stage_A(
        unsigned char* smem, const float* Asrc, int n0, int ld, int kOff, int t) {
#pragma unroll
    for (int i = 0; i < 16; i++) {
        int f = t + i * 256;
        int row = f >> 5, c4 = f & 31;
        int rc = n0 + row; if (rc > NN - 1) rc = NN - 1;
        float4 v = *(const float4*)(Asrc + (size_t)rc * ld + kOff + c4 * 4);
        uint32_t h01 = pk_bf16x2(v.x, v.y);
        uint32_t h23 = pk_bf16x2(v.z, v.w);
        uint32_t l01 = pk_bf16x2(v.x - bfbits2f(h01 & 0xFFFFu),
                                 v.y - bfbits2f(h01 >> 16));
        uint32_t l23 = pk_bf16x2(v.z - bfbits2f(h23 & 0xFFFFu),
                                 v.w - bfbits2f(h23 >> 16));
        uint32_t off = (uint32_t)row * 272 + (uint32_t)c4 * 8;
        *(uint2*)(smem + M32_AH + off) = make_uint2(h01, h23);
        *(uint2*)(smem + M32_AL + off) = make_uint2(l01, l23);
    }
}

// phase1 over WH: acc += ah*bh + al*bh
__device__ __forceinline__ void mma_phase1(
        float acc[2][8][4], uint32_t aBase, uint32_t bBase) {
#pragma unroll
    for (int ks = 0; ks < 8; ks++) {
        uint32_t ah0[4], ah1[4], al0[4], al1[4];
        ldsm4(aBase + M32_AH + ks * 32, ah0);
        ldsm4(aBase + M32_AH + KS + ks * 32, ah1);
        ldsm4(aBase + M32_AL + ks * 32, al0);
        ldsm4(aBase + M32_AL + KS + ks * 32, al1);
#pragma unroll
        for (int g = 0; g < 4; g++) {
            uint32_t bh[4];
            ldsm4t(bBase + (uint32_t)ks * KS + (uint32_t)g * 32, bh);
            mma_bf16(acc[0][g * 2],     ah0, bh);
            mma_bf16(acc[0][g * 2 + 1], ah0, bh + 2);
            mma_bf16(acc[1][g * 2],     ah1, bh);
            mma_bf16(acc[1][g * 2 + 1], ah1, bh + 2);
            mma_bf16(acc[0][g * 2],     al0, bh);
            mma_bf16(acc[0][g * 2 + 1], al0, bh + 2);
            mma_bf16(acc[1][g * 2],     al1, bh);
            mma_bf16(acc[1][g * 2 + 1], al1, bh + 2);
        }
    }
}
// phase2 over WL: acc += ah*bl
__device__ __forceinline__ void mma_phase2(
        float acc[2][8][4], uint32_t aBase, uint32_t bBase) {
#pragma unroll
    for (int ks = 0; ks < 8; ks++) {
        uint32_t ah0[4], ah1[4];
        ldsm4(aBase + M32_AH + ks * 32, ah0);
        ldsm4(aBase + M32_AH + KS + ks * 32, ah1);
#pragma unroll
        for (int g = 0; g < 4; g++) {
            uint32_t bl[4];
            ldsm4t(bBase + (uint32_t)ks * KS + (uint32_t)g * 32, bl);
            mma_bf16(acc[0][g * 2],     ah0, bl);
            mma_bf16(acc[0][g * 2 + 1], ah0, bl + 2);
            mma_bf16(acc[1][g * 2],     ah1, bl);
            mma_bf16(acc[1][g * 2 + 1], ah1, bl + 2);
        }
    }
}

// ==================== HMMA GEMM, M32 warps (sum path) ======================
// out = tanh(sum_ch A_ch @ W_ch (+ X@Wl) + add + b)
__global__ void __launch_bounds__(256, 2) tc_gemm32(
        int aWhich, const float* aExt, int nChunks, int wBase,
        int xWhich, const float* xExt, int xWIdx,
        int addWhich,
        const float* __restrict__ b,
        float* outExt, int outWhich) {
    extern __shared__ unsigned char smem[];
    uint32_t sb = smem_u32(smem);
    int t = threadIdx.x, wid = t >> 5, lane = t & 31;
    int wr = wid & 3, wc = wid >> 2;
    int n0 = blockIdx.x * 128;

    const float* A = selbuf(aWhich, (float*)aExt);
    const float* X = (xWIdx >= 0) ? selbuf(xWhich, (float*)xExt) : nullptr;
    const float* add = addWhich ? selbuf(addWhich, nullptr) : nullptr;
    float* out = selbuf(outWhich, outExt);

    float acc[2][8][4];
#pragma unroll
    for (int m = 0; m < 2; m++)
#pragma unroll
        for (int i = 0; i < 8; i++)
#pragma unroll
            for (int j = 0; j < 4; j++) acc[m][i][j] = 0.f;

    int ldA = nChunks * 128;
    int tot = nChunks + (X ? 1 : 0);

    uint32_t lmrow = (uint32_t)(lane & 15) * 272 + (uint32_t)(lane >> 4) * 16;
    uint32_t aBase = sb + (uint32_t)wr * (2 * KS) + lmrow;
    uint32_t bBase = sb + M32_W + lmrow + (uint32_t)wc * 128;

    for (int ch = 0; ch < tot; ch++) {
        const float* Asrc; int ld, kOff, wIdx;
        if (ch < nChunks) { Asrc = A; ld = ldA; kOff = ch * 128; wIdx = wBase + ch; }
        else              { Asrc = X; ld = 128; kOff = 0;        wIdx = xWIdx; }

        const unsigned char* wimg = g_wprep + (size_t)wIdx * WSTRIDE;

        __syncthreads();
        for (int i = t; i < 2176; i += 256)
            cp_async16(sb + M32_W + (uint32_t)i * 16, wimg + (size_t)i * 16);
        cp_commit();
        stage_A(smem, Asrc, n0, ld, kOff, t);
        cp_wait0();
        __syncthreads();

        mma_phase1(acc, aBase, bBase);
        __syncthreads();
        for (int i = t; i < 2176; i += 256)
            cp_async16(sb + M32_W + (uint32_t)i * 16, wimg + WHALF + (size_t)i * 16);
        cp_commit();
        cp_wait0();
        __syncthreads();
        mma_phase2(acc, aBase, bBase);
    }

    // ---- epilogue: (+add) + bias + tanh + store ----
#pragma unroll
    for (int m = 0; m < 2; m++) {
        int r0 = n0 + wr * 32 + m * 16 + (lane >> 2);
        int r1 = r0 + 8;
#pragma unroll
        for (int nt = 0; nt < 8; nt++) {
            int col = wc * 64 + nt * 8 + (lane & 3) * 2;
            float2 bb = *(const float2*)(b + col);
            if (r0 < NN) {
                float2 a0 = add ? *(const float2*)(add + (size_t)r0 * 128 + col)
                                : make_float2(0.f, 0.f);
                float2 o = make_float2(tanhf(acc[m][nt][0] + bb.x + a0.x),
                                       tanhf(acc[m][nt][1] + bb.y + a0.y));
                *(float2*)(out + (size_t)r0 * 128 + col) = o;
            }
            if (r1 < NN) {
                float2 a1 = add ? *(const float2*)(add + (size_t)r1 * 128 + col)
                                : make_float2(0.f, 0.f);
                float2 o = make_float2(tanhf(acc[m][nt][2] + bb.x + a1.x),
                                       tanhf(acc[m][nt][3] + bb.y + a1.y));
                *(float2*)(out + (size_t)r1 * 128 + col) = o;
            }
        }
    }
}

// ============ multi-output transform: H_r = A @ W_r, r=0..R-1 ==============
// One A staging serves all R relation GEMMs; raw fp32 output, relation-major.
__global__ void __launch_bounds__(256, 2) tc_xform(
        int aWhich, const float* aExt, int R, int wBase, int outWhich) {
    extern __shared__ unsigned char smem[];
    uint32_t sb = smem_u32(smem);
    int t = threadIdx.x, wid = t >> 5, lane = t & 31;
    int wr = wid & 3, wc = wid >> 2;
    int n0 = blockIdx.x * 128;

    const float* A = selbuf(aWhich, (float*)aExt);
    float* out = selbuf(outWhich, nullptr);

    uint32_t lmrow = (uint32_t)(lane & 15) * 272 + (uint32_t)(lane >> 4) * 16;
    uint32_t aBase = sb + (uint32_t)wr * (2 * KS) + lmrow;
    uint32_t bBase = sb + M32_W + lmrow + (uint32_t)wc * 128;

    stage_A(smem, A, n0, 128, 0, t);
    __syncthreads();

    for (int r = 0; r < R; r++) {
        const unsigned char* wimg = g_wprep + (size_t)(wBase + r) * WSTRIDE;

        float acc[2][8][4];
#pragma unroll
        for (int m = 0; m < 2; m++)
#pragma unroll
            for (int i = 0; i < 8; i++)
#pragma unroll
                for (int j = 0; j < 4; j++) acc[m][i][j] = 0.f;

        for (int i = t; i < 2176; i += 256)
            cp_async16(sb + M32_W + (uint32_t)i * 16, wimg + (size_t)i * 16);
        cp_commit();
        cp_wait0();
        __syncthreads();
        mma_phase1(acc, aBase, bBase);
        __syncthreads();
        for (int i = t; i < 2176; i += 256)
            cp_async16(sb + M32_W + (uint32_t)i * 16, wimg + WHALF + (size_t)i * 16);
        cp_commit();
        cp_wait0();
        __syncthreads();
        mma_phase2(acc, aBase, bBase);

        float* Hr = out + (size_t)r * NN * 128;
#pragma unroll
        for (int m = 0; m < 2; m++) {
            int r0 = n0 + wr * 32 + m * 16 + (lane >> 2);
            int r1 = r0 + 8;
#pragma unroll
            for (int nt = 0; nt < 8; nt++) {
                int col = wc * 64 + nt * 8 + (lane & 3) * 2;
                if (r0 < NN)
                    *(float2*)(Hr + (size_t)r0 * 128 + col) =
                        make_float2(acc[m][nt][0], acc[m][nt][1]);
                if (r1 < NN)
                    *(float2*)(Hr + (size_t)r1 * 128 + col) =
                        make_float2(acc[m][nt][2], acc[m][nt][3]);
            }
        }
        __syncthreads();   // all warps done reading WL before next WH copy
    }
}

// ==================== HMMA GEMM, M16 warps (hetero mean) ===================
// out = (1/nChunks)*sum_ch tanh(A_ch@W_ch + b_ch); A interleaved buckets.
#define SM_AH 0
#define SM_AL 17408
#define SM_W  34816
#define SMEM_MEAN 69632

__global__ void __launch_bounds__(256, 3) tc_gemm_mean(
        int aWhich, int nChunks, int wBase,
        const float* __restrict__ b,
        float* outExt, int outWhich) {
    extern __shared__ unsigned char smem[];
    uint32_t sb = smem_u32(smem);
    int t = threadIdx.x, wid = t >> 5, lane = t & 31;
    int wr = wid & 3, wc = wid >> 2;
    int n0 = blockIdx.x * 64;

    const float* A = selbuf(aWhich, nullptr);
    float* out = selbuf(outWhich, outExt);

    float acc[8][4];
    float fin[8][4];
#pragma unroll
    for (int i = 0; i < 8; i++)
#pragma unroll
        for (int j = 0; j < 4; j++) { acc[i][j] = 0.f; fin[i][j] = 0.f; }

    int ldA = nChunks * 128;

    uint32_t lmrow = (uint32_t)(lane & 15) * 272 + (uint32_t)(lane >> 4) * 16;
    uint32_t aAddrBase = sb + (uint32_t)wr * KS + lmrow;
    uint32_t bAddrBase = sb + SM_W + lmrow + (uint32_t)wc * 128;

    for (int ch = 0; ch < nChunks; ch++) {
        const unsigned char* wimg = g_wprep + (size_t)(wBase + ch) * WSTRIDE;

        __syncthreads();
        for (int i = t; i < 2176; i += 256)
            cp_async16(sb + SM_W + (uint32_t)i * 16, wimg + (size_t)i * 16);
        cp_commit();
#pragma unroll
        for (int i = 0; i < 8; i++) {
            int f = t + i * 256;
            int row = f >> 5, c4 = f & 31;
            int rc = n0 + row; if (rc > NN - 1) rc = NN - 1;
            float4 v = *(const float4*)(A + (size_t)rc * ldA + ch * 128 + c4 * 4);
            uint32_t h01 = pk_bf16x2(v.x, v.y);
            uint32_t h23 = pk_bf16x2(v.z, v.w);
            uint32_t l01 = pk_bf16x2(v.x - bfbits2f(h01 & 0xFFFFu),
                                     v.y - bfbits2f(h01 >> 16));
            uint32_t l23 = pk_bf16x2(v.z - bfbits2f(h23 & 0xFFFFu),
                                     v.w - bfbits2f(h23 >> 16));
            uint32_t off = (uint32_t)row * 272 + (uint32_t)c4 * 8;
            *(uint2*)(smem + SM_AH + off) = make_uint2(h01, h23);
            *(uint2*)(smem + SM_AL + off) = make_uint2(l01, l23);
        }
        cp_wait0();
        __syncthreads();

#pragma unroll
        for (int ks = 0; ks < 8; ks++) {
            uint32_t ah[4], al[4];
            ldsm4(aAddrBase + SM_AH + ks * 32, ah);
            ldsm4(aAddrBase + SM_AL + ks * 32, al);
#pragma unroll
            for (int g = 0; g < 4; g++) {
                uint32_t bh[4];
                ldsm4t(bAddrBase + (uint32_t)ks * KS + (uint32_t)g * 32, bh);
                mma_bf16(acc[g * 2],     ah, bh);
                mma_bf16(acc[g * 2 + 1], ah, bh + 2);
                mma_bf16(acc[g * 2],     al, bh);
                mma_bf16(acc[g * 2 + 1], al, bh + 2);
            }
        }
        __syncthreads();
        for (int i = t; i < 2176; i += 256)
            cp_async16(sb + SM_W + (uint32_t)i * 16, wimg + WHALF + (size_t)i * 16);
        cp_commit();
        cp_wait0();
        __syncthreads();

#pragma unroll
        for (int ks = 0; ks < 8; ks++) {
            uint32_t ah[4];
            ldsm4(aAddrBase + SM_AH + ks * 32, ah);
#pragma unroll
            for (int g = 0; g < 4; g++) {
                uint32_t bl[4];
                ldsm4t(bAddrBase + (uint32_t)ks * KS + (uint32_t)g * 32, bl);
                mma_bf16(acc[g * 2],     ah, bl);
                mma_bf16(acc[g * 2 + 1], ah, bl + 2);
            }
        }

#pragma unroll
        for (int nt = 0; nt < 8; nt++) {
            int col = wc * 64 + nt * 8 + (lane & 3) * 2;
            float2 bb = *(const float2*)(b + ch * 128 + col);
            fin[nt][0] += tanhf(acc[nt][0] + bb.x);
            fin[nt][1] += tanhf(acc[nt][1] + bb.y);
            fin[nt][2] += tanhf(acc[nt][2] + bb.x);
            fin[nt][3] += tanhf(acc[nt][3] + bb.y);
            acc[nt][0] = acc[nt][1] = acc[nt][2] = acc[nt][3] = 0.f;
        }
    }

    int r0 = n0 + wr * 16 + (lane >> 2);
    int r1 = r0 + 8;
    float s = 1.0f / (float)nChunks;
#pragma unroll
    for (int nt = 0; nt < 8; nt++) {
        int col = wc * 64 + nt * 8 + (lane & 3) * 2;
        if (r0 < NN) {
            float2 o = make_float2(fin[nt][0] * s, fin[nt][1] * s);
            *(float2*)(out + (size_t)r0 * 128 + col) = o;
        }
        if (r1 < NN) {
            float2 o = make_float2(fin[nt][2] * s, fin[nt][3] * s);
            *(float2*)(out + (size_t)r1 * 128 + col) = o;
        }
    }
}

// ---------------------------------------------------------------------------
extern "C" void kernel_launch(void* const* d_in, const int* in_sizes, int n_in,
                              void* d_out, int out_size) {
    const int*   gcn_src1 = (const int*)d_in[0];
    const int*   gcn_dst1 = (const int*)d_in[1];
    const int*   gcn_src2 = (const int*)d_in[2];
    const int*   gcn_dst2 = (const int*)d_in[3];
    const int*   rg_src1  = (const int*)d_in[4];
    const int*   rg_dst1  = (const int*)d_in[5];
    const int*   rg_et1   = (const int*)d_in[6];
    const int*   rg_src2  = (const int*)d_in[7];
    const int*   rg_dst2  = (const int*)d_in[8];
    const int*   rg_et2   = (const int*)d_in[9];
    const int*   het_src1 = (const int*)d_in[10];
    const int*   het_dst1 = (const int*)d_in[11];
    const int*   het_src2 = (const int*)d_in[12];
    const int*   het_dst2 = (const int*)d_in[13];
    const float* emb      = (const float*)d_in[14];
    const float* gcn_W1   = (const float*)d_in[15];
    const float* gcn_b1   = (const float*)d_in[16];
    const float* gcn_W2   = (const float*)d_in[17];
    const float* gcn_b2   = (const float*)d_in[18];
    const float* rg_W1    = (const float*)d_in[19];
    const float* rg_loop1 = (const float*)d_in[20];
    const float* rg_b1    = (const float*)d_in[21];
    const float* rg_W2    = (const float*)d_in[22];
    const float* rg_loop2 = (const float*)d_in[23];
    const float* rg_b2    = (const float*)d_in[24];
    const float* het_W1   = (const float*)d_in[25];
    const float* het_b1   = (const float*)d_in[26];
    const float* het_W2   = (const float*)d_in[27];
    const float* het_b2   = (const float*)d_in[28];

    float* out_hcf = (float*)d_out;
    float* out_hc  = out_hcf + (size_t)NN * D;
    float* out_hs  = out_hcf + (size_t)2 * NN * D;

    cudaFuncSetAttribute(tc_gemm32, cudaFuncAttributeMaxDynamicSharedMemorySize, SMEM_M32);
    cudaFuncSetAttribute(tc_xform, cudaFuncAttributeMaxDynamicSharedMemorySize, SMEM_M32);
    cudaFuncSetAttribute(tc_gemm_mean, cudaFuncAttributeMaxDynamicSharedMemorySize, SMEM_MEAN);

    const int ZB = 256, ZG = 2048;
    const int SG = 4096;                // grid-stride scatter blocks
    const int g32 = (NN + 127) / 128;   // 782
    const int g16 = (NN + 63) / 64;     // 1563

    // ---- prep on main stream, then fork ----
    prep_weights<<<28, 128>>>(gcn_W1, gcn_W2, rg_W1, rg_loop1, rg_W2, rg_loop2,
                              het_W1, het_W2);
    cudaEventRecord(g_eFork, 0);
    cudaStreamWaitEvent(g_s1, g_eFork, 0);
    cudaStreamWaitEvent(g_s2, g_eFork, 0);

    // ---- GCN branch (main stream): bucket=g_agg(2), temp=g_h(1) ----
    zero_kernel<<<ZG, ZB>>>(2, NN * 32);
    scatter_kernel<<<SG, 256>>>(0, emb, gcn_src1, gcn_dst1, nullptr, 0, 0, 1, 2, EH);
    tc_gemm32<<<g32, 256, SMEM_M32>>>(2, nullptr, 1, 0, 0, nullptr, -1, 0, gcn_b1, nullptr, 1);
    zero_kernel<<<ZG, ZB>>>(2, NN * 32);
    scatter_kernel<<<SG, 256>>>(1, nullptr, gcn_src2, gcn_dst2, nullptr, 0, 0, 1, 2, EH);
    tc_gemm32<<<g32, 256, SMEM_M32>>>(2, nullptr, 1, 1, 0, nullptr, -1, 0, gcn_b2, out_hcf, 0);

    // ---- RGCN branch (s1): transform-first ----
    // layer 1: H_r = emb @ rg_W1[r] -> gather-scatter into agg2 -> tanh(emb@loop1 + agg2 + b)
    zero_kernel<<<ZG, ZB, 0, g_s1>>>(7, NN * 32);
    tc_xform<<<g32, 256, SMEM_M32, g_s1>>>(0, emb, RRG, 2, 3);
    scatter_kernel<<<SG, 256, 0, g_s1>>>(3, nullptr, rg_src1, rg_dst1, rg_et1, 0, 1, 1, 7, EH);
    tc_gemm32<<<g32, 256, SMEM_M32, g_s1>>>(0, emb, 1, 10, 0, nullptr, -1, 7, rg_b1, nullptr, 5);
    // layer 2
    zero_kernel<<<ZG, ZB, 0, g_s1>>>(7, NN * 32);
    tc_xform<<<g32, 256, SMEM_M32, g_s1>>>(5, nullptr, RRG, 11, 3);
    scatter_kernel<<<SG, 256, 0, g_s1>>>(3, nullptr, rg_src2, rg_dst2, rg_et2, 0, 1, 1, 7, EH);
    tc_gemm32<<<g32, 256, SMEM_M32, g_s1>>>(5, nullptr, 1, 19, 0, nullptr, -1, 7, rg_b2, out_hc, 0);
    cudaEventRecord(g_eJoin1, g_s1);

    // ---- Hetero branch (s2): buckets=g_hb(4), temp=g_h3(6) ----
    zero_kernel<<<ZG, ZB, 0, g_s2>>>(4, NN * RHET * 32);
    scatter_kernel<<<SG, 256, 0, g_s2>>>(0, emb, het_src1, het_dst1, nullptr, EREL, 0, RHET, 4, EH);
    tc_gemm_mean<<<g16, 256, SMEM_MEAN, g_s2>>>(4, RHET, 20, het_b1, nullptr, 6);
    zero_kernel<<<ZG, ZB, 0, g_s2>>>(4, NN * RHET * 32);
    scatter_kernel<<<SG, 256, 0, g_s2>>>(6, nullptr, het_src2, het_dst2, nullptr, EREL, 0, RHET, 4, EH);
    tc_gemm_mean<<<g16, 256, SMEM_MEAN, g_s2>>>(4, RHET, 24, het_b2, out_hs, 0);
    cudaEventRecord(g_eJoin2, g_s2);

    // ---- join back to main stream ----
    cudaStreamWaitEvent(0, g_eJoin1, 0);
    cudaStreamWaitEvent(0, g_eJoin2, 0);
}